// round 1
// baseline (speedup 1.0000x reference)
#include <cuda_runtime.h>

#define NLAYERS 4
#define BATCH   8
#define CCH     256
#define HH      32
#define WWW     32
#define NHEADS  8
#define DHEAD   64
#define SPI     1024      // H*W
#define NPIX    8192      // B*H*W
#define NTOK    65536     // NPIX*NHEADS
#define KHH     512       // NHEADS*DHEAD

// ---------------- scratch (static device globals; no allocation) ----------------
__device__ __align__(16) float g_x[BATCH*CCH*SPI];
__device__ __align__(16) float g_keys[NLAYERS][NTOK*DHEAD];
__device__ __align__(16) float g_vals[NLAYERS][NTOK*DHEAD];
__device__ __align__(16) float g_q[NTOK*DHEAD];
__device__ __align__(16) float g_o[BATCH*KHH*SPI];
__device__ __align__(16) float g_h[BATCH*CCH*SPI];
__device__ float g_bnsum[CCH];
__device__ float g_bnsq[CCH];
__device__ float g_scale[CCH];
__device__ float g_shift[CCH];

// ---------------- packed f32x2 helpers (FFMA2 path, 2x fp32 rate) ----------------
__device__ __forceinline__ unsigned long long pack2s(float x) {
    unsigned long long r;
    unsigned int xi = __float_as_uint(x);
    asm("mov.b64 %0, {%1, %2};" : "=l"(r) : "r"(xi), "r"(xi));
    return r;
}
__device__ __forceinline__ void fma2(unsigned long long& d, unsigned long long a, unsigned long long b) {
    asm("fma.rn.f32x2 %0, %1, %2, %0;" : "+l"(d) : "l"(a), "l"(b));
}
__device__ __forceinline__ float2 unpack2(unsigned long long v) {
    unsigned int lo, hi;
    asm("mov.b64 {%0, %1}, %2;" : "=r"(lo), "=r"(hi) : "l"(v));
    return make_float2(__uint_as_float(lo), __uint_as_float(hi));
}

// ---------------- GEMM micro kernel: BM=64, BN=128, BK=8, 256 thr, 4x8 micro ----
__device__ __forceinline__ void micro8(const float (&As)[8][64], const float (&Bs)[8][128],
                                       unsigned long long (&acc)[4][4], int tm, int tn) {
#pragma unroll
    for (int kk = 0; kk < 8; kk++) {
        float4 a4 = *(const float4*)&As[kk][tm*4];
        unsigned long long b[4];
        b[0] = *(const unsigned long long*)&Bs[kk][tn*4];
        b[1] = *(const unsigned long long*)&Bs[kk][tn*4+2];
        b[2] = *(const unsigned long long*)&Bs[kk][64+tn*4];
        b[3] = *(const unsigned long long*)&Bs[kk][64+tn*4+2];
        unsigned long long ap;
        ap = pack2s(a4.x);
#pragma unroll
        for (int jc = 0; jc < 4; jc++) fma2(acc[0][jc], ap, b[jc]);
        ap = pack2s(a4.y);
#pragma unroll
        for (int jc = 0; jc < 4; jc++) fma2(acc[1][jc], ap, b[jc]);
        ap = pack2s(a4.z);
#pragma unroll
        for (int jc = 0; jc < 4; jc++) fma2(acc[2][jc], ap, b[jc]);
        ap = pack2s(a4.w);
#pragma unroll
        for (int jc = 0; jc < 4; jc++) fma2(acc[3][jc], ap, b[jc]);
    }
}

__device__ __forceinline__ void unpack_acc(const unsigned long long (&acc)[4][4], float (&v)[4][8]) {
#pragma unroll
    for (int i = 0; i < 4; i++)
#pragma unroll
        for (int jc = 0; jc < 4; jc++) {
            float2 t = unpack2(acc[i][jc]);
            v[i][2*jc]   = t.x;
            v[i][2*jc+1] = t.y;
        }
}

// ---------------- copy in/out ----------------
__global__ void copy_in(const float* __restrict__ x) {
    int i = blockIdx.x * 256 + threadIdx.x;
    ((float4*)g_x)[i] = ((const float4*)x)[i];
}
__global__ void copy_out(float* __restrict__ out) {
    int i = blockIdx.x * 256 + threadIdx.x;
    ((float4*)out)[i] = ((const float4*)g_x)[i];
}

// ---------------- fused QKV 1x1 conv (GEMM) ----------------
// grid (64, 24): by/8 -> type (0=k,1=q,2=v), by%8 -> head block (M=512 per type)
__global__ __launch_bounds__(256) void qkv_gemm(
    const float* __restrict__ Wk, const float* __restrict__ Wq, const float* __restrict__ Wv,
    const float* __restrict__ bk, const float* __restrict__ bq, const float* __restrict__ bv,
    int l)
{
    __shared__ float As[8][64];
    __shared__ float Bs[8][128];
    int tid  = threadIdx.x;
    int by   = blockIdx.y;
    int type = by >> 3, mb = by & 7;
    const float* Wt = (type == 0) ? Wk : ((type == 1) ? Wq : Wv);
    const float* bt = (type == 0) ? bk : ((type == 1) ? bq : bv);
    float* outb = (type == 0) ? g_keys[l] : ((type == 1) ? g_q : g_vals[l]);

    int pbase = blockIdx.x * 128;
    int bimg  = pbase >> 10;
    int sbase = pbase & 1023;
    const float* xin = g_x + bimg * (CCH * SPI);

    int tm = tid >> 4, tn = tid & 15;
    int arow = tid >> 2, acol = (tid & 3) * 2;
    int bkk = tid >> 5, bn4 = (tid & 31) * 4;

    unsigned long long acc[4][4];
#pragma unroll
    for (int i = 0; i < 4; i++)
#pragma unroll
        for (int j = 0; j < 4; j++) acc[i][j] = 0ull;

    for (int k0 = 0; k0 < CCH; k0 += 8) {
        float2 av = *(const float2*)&Wt[(mb*64 + arow) * CCH + k0 + acol];
        float4 bv4 = *(const float4*)&xin[(k0 + bkk) * SPI + sbase + bn4];
        As[acol][arow]   = av.x;
        As[acol+1][arow] = av.y;
        *(float4*)&Bs[bkk][bn4] = bv4;
        __syncthreads();
        micro8(As, Bs, acc, tm, tn);
        __syncthreads();
    }

    float v[4][8];
    unpack_acc(acc, v);
    float4 b4 = *(const float4*)&bt[mb*64 + tm*4];
    int head = mb;
#pragma unroll
    for (int j = 0; j < 8; j++) {
        int n = (j < 4) ? (tn*4 + j) : (64 + tn*4 + (j - 4));
        int p = pbase + n;
        int ntok = p * NHEADS + head;
        float4 o4 = make_float4(v[0][j] + b4.x, v[1][j] + b4.y, v[2][j] + b4.z, v[3][j] + b4.w);
        *(float4*)&outb[ntok * DHEAD + tm*4] = o4;
    }
}

// ---------------- attention (1 warp / token) ----------------
__global__ __launch_bounds__(256) void attn_kernel(int l) {
    int warp = threadIdx.x >> 5, lane = threadIdx.x & 31;
    int tok = blockIdx.x * 8 + warp;

    float2 q = ((const float2*)&g_q[tok * DHEAD])[lane];
    q.x *= 0.125f; q.y *= 0.125f;   // / sqrt(64)

    float sc[5];
#pragma unroll 4
    for (int t = 0; t <= l; t++) {
        float2 kv = ((const float2*)&g_keys[t][tok * DHEAD])[lane];
        float p = q.x * kv.x + q.y * kv.y;
#pragma unroll
        for (int o = 16; o; o >>= 1) p += __shfl_xor_sync(0xffffffffu, p, o);
        sc[t] = p;
    }
    sc[l + 1] = 0.0f;               // zero key
    int T = l + 2;

    float mx = sc[0];
    for (int t = 1; t < T; t++) mx = fmaxf(mx, sc[t]);
    float e[5], sum = 0.0f;
    for (int t = 0; t < T; t++) { e[t] = expf(sc[t] - mx); sum += e[t]; }
    float inv = 1.0f / sum;
    float a[5];
    for (int t = 0; t < T; t++) a[t] = e[t] * inv;

    if (T == 5) {  // sparse top-4: delta = 4th-largest(=2nd-smallest of 5) + eps
        float mn1 = fminf(fminf(a[0], a[1]), fminf(fminf(a[2], a[3]), a[4]));
        float mn2 = 1e30f; bool used = false;
        for (int t = 0; t < 5; t++) {
            if (!used && a[t] == mn1) used = true;
            else mn2 = fminf(mn2, a[t]);
        }
        float delta = mn2 + 1e-7f;
        float s2 = 0.0f;
        for (int t = 0; t < 5; t++) { a[t] = fmaxf(a[t] - delta, 0.0f); s2 += a[t]; }
        float r = 1.0f / (s2 + 1e-7f);
        for (int t = 0; t < 5; t++) a[t] *= r;
    }

    float2 oacc = make_float2(0.0f, 0.0f);
#pragma unroll 4
    for (int t = 0; t <= l; t++) {
        float2 vv = ((const float2*)&g_vals[t][tok * DHEAD])[lane];
        oacc.x += a[t] * vv.x;
        oacc.y += a[t] * vv.y;
    }

    int p = tok >> 3, head = tok & 7;
    int bimg = p >> 10, s = p & 1023;
    float* op = g_o + bimg * (KHH * SPI) + (head * DHEAD + lane * 2) * SPI + s;
    op[0]   = oacc.x;
    op[SPI] = oacc.y;
}

// ---------------- BN helpers ----------------
__global__ void bn_zero() { g_bnsum[threadIdx.x] = 0.0f; g_bnsq[threadIdx.x] = 0.0f; }
__global__ void bn_fin(const float* __restrict__ g, const float* __restrict__ b) {
    int c = threadIdx.x;
    float m = g_bnsum[c] * (1.0f / (float)NPIX);
    float v = g_bnsq[c] * (1.0f / (float)NPIX) - m * m;
    float sc = g[c] * rsqrtf(v + 1e-5f);
    g_scale[c] = sc;
    g_shift[c] = b[c] - m * sc;
}

// ---------------- conv1: 3x3, 512->256, + bias, writes g_h, BN partial stats ----
__global__ __launch_bounds__(256) void conv1_gemm(const float* __restrict__ Wt, const float* __restrict__ bt) {
    __shared__ float As[8][64];
    __shared__ float Bs[8][128];
    __shared__ float redS[64][17];
    __shared__ float redQ[64][17];
    const int Kdim = KHH * 9;  // 4608
    int tid = threadIdx.x;
    int pbase = blockIdx.x * 128;
    int mb = blockIdx.y;
    int bimg = pbase >> 10, sb = pbase & 1023;
    const float* in0 = g_o + bimg * (KHH * SPI);
    int tm = tid >> 4, tn = tid & 15;
    int arow = tid >> 2, acol = (tid & 3) * 2;
    int bkk = tid >> 5, bn4 = (tid & 31) * 4;

    unsigned long long acc[4][4];
#pragma unroll
    for (int i = 0; i < 4; i++)
#pragma unroll
        for (int j = 0; j < 4; j++) acc[i][j] = 0ull;

    for (int k0 = 0; k0 < Kdim; k0 += 8) {
        float2 av = *(const float2*)&Wt[(mb*64 + arow) * Kdim + k0 + acol];
        int kg = k0 + bkk;
        int cin = kg / 9;
        int jj = kg - cin * 9;
        int dy = jj / 3 - 1;
        int dx = jj - (jj / 3) * 3 - 1;
        const float* src = in0 + cin * SPI;
        float bvv[4];
#pragma unroll
        for (int e = 0; e < 4; e++) {
            int s = sb + bn4 + e;
            int yy = (s >> 5) + dy, xx = (s & 31) + dx;
            bvv[e] = (yy >= 0 && yy < HH && xx >= 0 && xx < WWW) ? src[yy * WWW + xx] : 0.0f;
        }
        As[acol][arow]   = av.x;
        As[acol+1][arow] = av.y;
        *(float4*)&Bs[bkk][bn4] = make_float4(bvv[0], bvv[1], bvv[2], bvv[3]);
        __syncthreads();
        micro8(As, Bs, acc, tm, tn);
        __syncthreads();
    }

    float v[4][8];
    unpack_acc(acc, v);
    float4 b4 = *(const float4*)&bt[mb*64 + tm*4];
    float bb[4] = {b4.x, b4.y, b4.z, b4.w};
    float* hbase = g_h + bimg * (CCH * SPI);
#pragma unroll
    for (int i = 0; i < 4; i++) {
        int o = mb*64 + tm*4 + i;
        float* dst = hbase + o * SPI + sb;
        float4 lo = make_float4(v[i][0]+bb[i], v[i][1]+bb[i], v[i][2]+bb[i], v[i][3]+bb[i]);
        float4 hi = make_float4(v[i][4]+bb[i], v[i][5]+bb[i], v[i][6]+bb[i], v[i][7]+bb[i]);
        *(float4*)&dst[tn*4]      = lo;
        *(float4*)&dst[64 + tn*4] = hi;
        float s = lo.x+lo.y+lo.z+lo.w + hi.x+hi.y+hi.z+hi.w;
        float qq = lo.x*lo.x+lo.y*lo.y+lo.z*lo.z+lo.w*lo.w
                 + hi.x*hi.x+hi.y*hi.y+hi.z*hi.z+hi.w*hi.w;
        redS[tm*4+i][tn] = s;
        redQ[tm*4+i][tn] = qq;
    }
    __syncthreads();
    if (tid < 64) {
        float s = 0.0f, qq = 0.0f;
#pragma unroll
        for (int t = 0; t < 16; t++) { s += redS[tid][t]; qq += redQ[tid][t]; }
        atomicAdd(&g_bnsum[mb*64 + tid], s);
        atomicAdd(&g_bnsq[mb*64 + tid], qq);
    }
}

// ---------------- conv2: 3x3, 256->256, input = relu(bn(g_h)) on the fly,
// ----------------  epilogue: g_x += gamma * (conv + bias)
__global__ __launch_bounds__(256) void conv2_gemm(const float* __restrict__ Wt, const float* __restrict__ bt,
                                                  const float* __restrict__ gammas, int l) {
    __shared__ float As[8][64];
    __shared__ float Bs[8][128];
    const int Kdim = CCH * 9;  // 2304
    int tid = threadIdx.x;
    int pbase = blockIdx.x * 128;
    int mb = blockIdx.y;
    int bimg = pbase >> 10, sb = pbase & 1023;
    const float* in0 = g_h + bimg * (CCH * SPI);
    int tm = tid >> 4, tn = tid & 15;
    int arow = tid >> 2, acol = (tid & 3) * 2;
    int bkk = tid >> 5, bn4 = (tid & 31) * 4;

    unsigned long long acc[4][4];
#pragma unroll
    for (int i = 0; i < 4; i++)
#pragma unroll
        for (int j = 0; j < 4; j++) acc[i][j] = 0ull;

    for (int k0 = 0; k0 < Kdim; k0 += 8) {
        float2 av = *(const float2*)&Wt[(mb*64 + arow) * Kdim + k0 + acol];
        int kg = k0 + bkk;
        int cin = kg / 9;
        int jj = kg - cin * 9;
        int dy = jj / 3 - 1;
        int dx = jj - (jj / 3) * 3 - 1;
        const float* src = in0 + cin * SPI;
        float scl = g_scale[cin], sh = g_shift[cin];
        float bvv[4];
#pragma unroll
        for (int e = 0; e < 4; e++) {
            int s = sb + bn4 + e;
            int yy = (s >> 5) + dy, xx = (s & 31) + dx;
            float val = 0.0f;
            if (yy >= 0 && yy < HH && xx >= 0 && xx < WWW)
                val = fmaxf(src[yy * WWW + xx] * scl + sh, 0.0f);
            bvv[e] = val;
        }
        As[acol][arow]   = av.x;
        As[acol+1][arow] = av.y;
        *(float4*)&Bs[bkk][bn4] = make_float4(bvv[0], bvv[1], bvv[2], bvv[3]);
        __syncthreads();
        micro8(As, Bs, acc, tm, tn);
        __syncthreads();
    }

    float v[4][8];
    unpack_acc(acc, v);
    float4 b4 = *(const float4*)&bt[mb*64 + tm*4];
    float bb[4] = {b4.x, b4.y, b4.z, b4.w};
    float gam = gammas[l];
    float* xbase = g_x + bimg * (CCH * SPI);
#pragma unroll
    for (int i = 0; i < 4; i++) {
        int o = mb*64 + tm*4 + i;
        float* dst = xbase + o * SPI + sb;
        float4 lo = *(float4*)&dst[tn*4];
        lo.x += gam * (v[i][0] + bb[i]);
        lo.y += gam * (v[i][1] + bb[i]);
        lo.z += gam * (v[i][2] + bb[i]);
        lo.w += gam * (v[i][3] + bb[i]);
        *(float4*)&dst[tn*4] = lo;
        float4 hi = *(float4*)&dst[64 + tn*4];
        hi.x += gam * (v[i][4] + bb[i]);
        hi.y += gam * (v[i][5] + bb[i]);
        hi.z += gam * (v[i][6] + bb[i]);
        hi.w += gam * (v[i][7] + bb[i]);
        *(float4*)&dst[64 + tn*4] = hi;
    }
}

// ---------------- launch ----------------
extern "C" void kernel_launch(void* const* d_in, const int* in_sizes, int n_in,
                              void* d_out, int out_size) {
    const float* x   = (const float*)d_in[0];
    const float* kw  = (const float*)d_in[1];
    const float* kb  = (const float*)d_in[2];
    const float* qw  = (const float*)d_in[3];
    const float* qb  = (const float*)d_in[4];
    const float* vw  = (const float*)d_in[5];
    const float* vb  = (const float*)d_in[6];
    const float* ow1 = (const float*)d_in[7];
    const float* ob1 = (const float*)d_in[8];
    const float* bng = (const float*)d_in[9];
    const float* bnb = (const float*)d_in[10];
    const float* ow2 = (const float*)d_in[11];
    const float* ob2 = (const float*)d_in[12];
    const float* gam = (const float*)d_in[13];

    copy_in<<<2048, 256>>>(x);
    for (int l = 0; l < NLAYERS; l++) {
        qkv_gemm<<<dim3(64, 24), 256>>>(kw + l * KHH * CCH, qw + l * KHH * CCH, vw + l * KHH * CCH,
                                        kb + l * KHH, qb + l * KHH, vb + l * KHH, l);
        attn_kernel<<<8192, 256>>>(l);
        bn_zero<<<1, 256>>>();
        conv1_gemm<<<dim3(64, 4), 256>>>(ow1 + l * CCH * KHH * 9, ob1 + l * CCH);
        bn_fin<<<1, 256>>>(bng + l * CCH, bnb + l * CCH);
        conv2_gemm<<<dim3(64, 4), 256>>>(ow2 + l * CCH * CCH * 9, ob2 + l * CCH, gam, l);
    }
    copy_out<<<2048, 256>>>((float*)d_out);
}

// round 2
// speedup vs baseline: 2.0454x; 2.0454x over previous
#include <cuda_runtime.h>

#define NLAYERS 4
#define BATCH   8
#define CCH     256
#define HH      32
#define WWW     32
#define NHEADS  8
#define DHEAD   64
#define SPI     1024      // H*W
#define NPIX    8192      // B*H*W
#define NTOK    65536     // NPIX*NHEADS
#define KHH     512       // NHEADS*DHEAD

// ---------------- scratch (static device globals; no allocation) ----------------
__device__ __align__(16) float g_x[BATCH*CCH*SPI];
__device__ __align__(16) float g_keys[NLAYERS][NTOK*DHEAD];
__device__ __align__(16) float g_vals[NLAYERS][NTOK*DHEAD];
__device__ __align__(16) float g_q[NTOK*DHEAD];
__device__ __align__(16) float g_o[BATCH*KHH*SPI];
__device__ __align__(16) float g_h[BATCH*CCH*SPI];
__device__ float g_bnsum[CCH];
__device__ float g_bnsq[CCH];
__device__ float g_scale[CCH];
__device__ float g_shift[CCH];

// ---------------- tf32 helpers ----------------
__device__ __forceinline__ unsigned f2tf(float x) {
    unsigned r;
    asm("cvt.rna.tf32.f32 %0, %1;" : "=r"(r) : "f"(x));
    return r;
}
__device__ __forceinline__ void mma8(float (&d)[4], const unsigned (&a)[4], const unsigned (&b)[2]) {
    asm volatile(
        "mma.sync.aligned.m16n8k8.row.col.f32.tf32.tf32.f32 "
        "{%0,%1,%2,%3}, {%4,%5,%6,%7}, {%8,%9}, {%0,%1,%2,%3};"
        : "+f"(d[0]), "+f"(d[1]), "+f"(d[2]), "+f"(d[3])
        : "r"(a[0]), "r"(a[1]), "r"(a[2]), "r"(a[3]), "r"(b[0]), "r"(b[1]));
}

// ---------------- copy in/out ----------------
__global__ void copy_in(const float* __restrict__ x) {
    int i = blockIdx.x * 256 + threadIdx.x;
    ((float4*)g_x)[i] = ((const float4*)x)[i];
}
__global__ void copy_out(float* __restrict__ out) {
    int i = blockIdx.x * 256 + threadIdx.x;
    ((float4*)out)[i] = ((const float4*)g_x)[i];
}

// ---------------- QKV 1x1 conv: tf32 tensor GEMM ----------------
// grid (64, 12): by>>2 -> type (0=k,1=q,2=v), by&3 -> 128-row block within 512
__global__ __launch_bounds__(256) void qkv_gemm(
    const float* __restrict__ Wk, const float* __restrict__ Wq, const float* __restrict__ Wv,
    const float* __restrict__ bk, const float* __restrict__ bq, const float* __restrict__ bv,
    int l)
{
    __shared__ unsigned As[128*36];   // A[m][k], stride 36 (conflict-free)
    __shared__ unsigned Bs[32*136];   // B[k][n], stride 136 (conflict-free)
    int tid = threadIdx.x;
    int warp = tid >> 5, lane = tid & 31;
    int g = lane >> 2, l4 = lane & 3;
    int wm = warp & 1, wn = warp >> 1;
    int by = blockIdx.y, type = by >> 2, mb = by & 3;
    const float* Wt = (type == 0) ? Wk : ((type == 1) ? Wq : Wv);
    const float* bt = (type == 0) ? bk : ((type == 1) ? bq : bv);
    float* outb = (type == 0) ? g_keys[l] : ((type == 1) ? g_q : g_vals[l]);

    int pbase = blockIdx.x * 128;
    int bimg = pbase >> 10, sbase = pbase & 1023;
    const float* xin = g_x + bimg * (CCH * SPI);

    float acc[4][4][4];
#pragma unroll
    for (int mt = 0; mt < 4; mt++)
#pragma unroll
        for (int nt = 0; nt < 4; nt++)
#pragma unroll
            for (int r = 0; r < 4; r++) acc[mt][nt][r] = 0.0f;

    int arow = tid >> 1, ahalf = (tid & 1) * 16;
    int bcin = tid >> 3, bseg = (tid & 7) * 16;
    const float* aptr = Wt + (mb * 128 + arow) * CCH + ahalf;

    for (int c = 0; c < 8; c++) {            // K = 256 in chunks of 32
        const float4* ap = (const float4*)(aptr + c * 32);
#pragma unroll
        for (int j = 0; j < 4; j++) {
            float4 v = ap[j];
            uint4 u = make_uint4(f2tf(v.x), f2tf(v.y), f2tf(v.z), f2tf(v.w));
            *(uint4*)&As[arow*36 + ahalf + j*4] = u;
        }
        const float4* bp = (const float4*)(xin + (c*32 + bcin) * SPI + sbase + bseg);
#pragma unroll
        for (int j = 0; j < 4; j++) {
            float4 v = bp[j];
            uint4 u = make_uint4(f2tf(v.x), f2tf(v.y), f2tf(v.z), f2tf(v.w));
            *(uint4*)&Bs[bcin*136 + bseg + j*4] = u;
        }
        __syncthreads();
#pragma unroll
        for (int ks = 0; ks < 4; ks++) {
            unsigned a[4][4], b[4][2];
#pragma unroll
            for (int mt = 0; mt < 4; mt++) {
                int r = wm*64 + mt*16 + g;
                a[mt][0] = As[r*36 + ks*8 + l4];
                a[mt][1] = As[(r+8)*36 + ks*8 + l4];
                a[mt][2] = As[r*36 + ks*8 + l4 + 4];
                a[mt][3] = As[(r+8)*36 + ks*8 + l4 + 4];
            }
#pragma unroll
            for (int nt = 0; nt < 4; nt++) {
                int n = wn*32 + nt*8 + g;
                b[nt][0] = Bs[(ks*8 + l4)*136 + n];
                b[nt][1] = Bs[(ks*8 + l4 + 4)*136 + n];
            }
#pragma unroll
            for (int mt = 0; mt < 4; mt++)
#pragma unroll
                for (int nt = 0; nt < 4; nt++)
                    mma8(acc[mt][nt], a[mt], b[nt]);
        }
        __syncthreads();
    }

    // epilogue: out[p*512 + m] = acc + bias   (token-flat layout)
#pragma unroll
    for (int mt = 0; mt < 4; mt++)
#pragma unroll
        for (int half = 0; half < 2; half++) {
            int mg = mb*128 + wm*64 + mt*16 + g + half*8;
            float bias = bt[mg];
#pragma unroll
            for (int nt = 0; nt < 4; nt++) {
                int p = pbase + wn*32 + nt*8 + l4*2;
                outb[p*512 + mg]       = acc[mt][nt][half*2]     + bias;
                outb[(p+1)*512 + mg]   = acc[mt][nt][half*2 + 1] + bias;
            }
        }
}

// ---------------- attention (1 warp / token) ----------------
__global__ __launch_bounds__(256) void attn_kernel(int l) {
    int warp = threadIdx.x >> 5, lane = threadIdx.x & 31;
    int tok = blockIdx.x * 8 + warp;

    float2 q = ((const float2*)&g_q[tok * DHEAD])[lane];
    q.x *= 0.125f; q.y *= 0.125f;

    float sc[5];
#pragma unroll 4
    for (int t = 0; t <= l; t++) {
        float2 kv = ((const float2*)&g_keys[t][tok * DHEAD])[lane];
        float p = q.x * kv.x + q.y * kv.y;
#pragma unroll
        for (int o = 16; o; o >>= 1) p += __shfl_xor_sync(0xffffffffu, p, o);
        sc[t] = p;
    }
    sc[l + 1] = 0.0f;
    int T = l + 2;

    float mx = sc[0];
    for (int t = 1; t < T; t++) mx = fmaxf(mx, sc[t]);
    float e[5], sum = 0.0f;
    for (int t = 0; t < T; t++) { e[t] = expf(sc[t] - mx); sum += e[t]; }
    float inv = 1.0f / sum;
    float a[5];
    for (int t = 0; t < T; t++) a[t] = e[t] * inv;

    if (T == 5) {
        float mn1 = fminf(fminf(a[0], a[1]), fminf(fminf(a[2], a[3]), a[4]));
        float mn2 = 1e30f; bool used = false;
        for (int t = 0; t < 5; t++) {
            if (!used && a[t] == mn1) used = true;
            else mn2 = fminf(mn2, a[t]);
        }
        float delta = mn2 + 1e-7f;
        float s2 = 0.0f;
        for (int t = 0; t < 5; t++) { a[t] = fmaxf(a[t] - delta, 0.0f); s2 += a[t]; }
        float r = 1.0f / (s2 + 1e-7f);
        for (int t = 0; t < 5; t++) a[t] *= r;
    }

    float2 oacc = make_float2(0.0f, 0.0f);
#pragma unroll 4
    for (int t = 0; t <= l; t++) {
        float2 vv = ((const float2*)&g_vals[t][tok * DHEAD])[lane];
        oacc.x += a[t] * vv.x;
        oacc.y += a[t] * vv.y;
    }

    int p = tok >> 3, head = tok & 7;
    int bimg = p >> 10, s = p & 1023;
    float* op = g_o + bimg * (KHH * SPI) + (head * DHEAD + lane * 2) * SPI + s;
    op[0]   = oacc.x;
    op[SPI] = oacc.y;
}

// ---------------- BN helpers ----------------
__global__ void bn_zero() { g_bnsum[threadIdx.x] = 0.0f; g_bnsq[threadIdx.x] = 0.0f; }
__global__ void bn_fin(const float* __restrict__ g, const float* __restrict__ b) {
    int c = threadIdx.x;
    float m = g_bnsum[c] * (1.0f / (float)NPIX);
    float v = g_bnsq[c] * (1.0f / (float)NPIX) - m * m;
    float sc = g[c] * rsqrtf(v + 1e-5f);
    g_scale[c] = sc;
    g_shift[c] = b[c] - m * sc;
}

// ---------------- conv1: 3x3, 512->256, tf32 tensor; halo-staged im2col ----
// grid (64, 2). BK = 72 (8 cins x 9 taps), 64 chunks.
__global__ __launch_bounds__(256) void conv1_gemm(const float* __restrict__ Wt, const float* __restrict__ bt) {
    __shared__ unsigned As[128*76];  // A[m][k], stride 76 (conflict-free)
    __shared__ unsigned Hs[8*204];   // halo: [cin][6 rows][34 cols]
    const int Kdim = KHH * 9;        // 4608
    int tid = threadIdx.x;
    int warp = tid >> 5, lane = tid & 31;
    int g = lane >> 2, l4 = lane & 3;
    int wm = warp & 1, wn = warp >> 1;
    int mbase = blockIdx.y * 128;
    int pbase = blockIdx.x * 128;
    int bimg = pbase >> 10, sbase = pbase & 1023;
    int r0 = sbase >> 5;
    const float* in0 = g_o + bimg * (KHH * SPI);

    int koffA[9], koffB[9];
#pragma unroll
    for (int ks = 0; ks < 9; ks++) {
        int k = ks*8 + l4;
        int cin = k / 9, jj = k - cin*9;
        koffA[ks] = cin*204 + (jj/3)*34 + (jj%3);
        k += 4; cin = k / 9; jj = k - cin*9;
        koffB[ks] = cin*204 + (jj/3)*34 + (jj%3);
    }
    int pixoff[4];
#pragma unroll
    for (int nt = 0; nt < 4; nt++) pixoff[nt] = wn*34 + nt*8 + g;

    float acc[4][4][4];
#pragma unroll
    for (int mt = 0; mt < 4; mt++)
#pragma unroll
        for (int nt = 0; nt < 4; nt++)
#pragma unroll
            for (int r = 0; r < 4; r++) acc[mt][nt][r] = 0.0f;

    int arow = tid >> 1, ahalf = (tid & 1) * 36;
    const float* aptr = Wt + (mbase + arow) * Kdim + ahalf;

    for (int ch = 0; ch < 64; ch++) {
        int cin0 = ch * 8;
        for (int idx = tid; idx < 1632; idx += 256) {
            int cin = idx / 204, rem = idx - cin*204;
            int rr = rem / 34, cc = rem - rr*34;
            int yy = r0 - 1 + rr, xx = cc - 1;
            float v = 0.0f;
            if (yy >= 0 && yy < HH && xx >= 0 && xx < WWW)
                v = in0[(cin0 + cin) * SPI + yy*WWW + xx];
            Hs[idx] = f2tf(v);
        }
        const float4* ap = (const float4*)(aptr + cin0*9);
#pragma unroll
        for (int j = 0; j < 9; j++) {
            float4 v = ap[j];
            uint4 u = make_uint4(f2tf(v.x), f2tf(v.y), f2tf(v.z), f2tf(v.w));
            *(uint4*)&As[arow*76 + ahalf + j*4] = u;
        }
        __syncthreads();
#pragma unroll
        for (int ks = 0; ks < 9; ks++) {
            unsigned a[4][4], b[4][2];
#pragma unroll
            for (int mt = 0; mt < 4; mt++) {
                int r = wm*64 + mt*16 + g;
                a[mt][0] = As[r*76 + ks*8 + l4];
                a[mt][1] = As[(r+8)*76 + ks*8 + l4];
                a[mt][2] = As[r*76 + ks*8 + l4 + 4];
                a[mt][3] = As[(r+8)*76 + ks*8 + l4 + 4];
            }
#pragma unroll
            for (int nt = 0; nt < 4; nt++) {
                b[nt][0] = Hs[koffA[ks] + pixoff[nt]];
                b[nt][1] = Hs[koffB[ks] + pixoff[nt]];
            }
#pragma unroll
            for (int mt = 0; mt < 4; mt++)
#pragma unroll
                for (int nt = 0; nt < 4; nt++)
                    mma8(acc[mt][nt], a[mt], b[nt]);
        }
        __syncthreads();
    }

    // epilogue: bias, store g_h, BN partial sums
    float* hbase = g_h + bimg * (CCH * SPI);
#pragma unroll
    for (int mt = 0; mt < 4; mt++)
#pragma unroll
        for (int half = 0; half < 2; half++) {
            int chn = mbase + wm*64 + mt*16 + g + half*8;
            float bias = bt[chn];
            float s = 0.0f, qq = 0.0f;
#pragma unroll
            for (int nt = 0; nt < 4; nt++) {
                float v0 = acc[mt][nt][half*2]     + bias;
                float v1 = acc[mt][nt][half*2 + 1] + bias;
                int n = wn*32 + nt*8 + l4*2;
                *(float2*)&hbase[chn * SPI + sbase + n] = make_float2(v0, v1);
                s += v0 + v1;
                qq += v0*v0 + v1*v1;
            }
            s  += __shfl_xor_sync(0xffffffffu, s, 1);
            s  += __shfl_xor_sync(0xffffffffu, s, 2);
            qq += __shfl_xor_sync(0xffffffffu, qq, 1);
            qq += __shfl_xor_sync(0xffffffffu, qq, 2);
            if (l4 == 0) {
                atomicAdd(&g_bnsum[chn], s);
                atomicAdd(&g_bnsq[chn], qq);
            }
        }
}

// ---------------- conv2: 3x3, 256->256, BN+ReLU fused in halo stage, residual ----
// grid (64, 2). BK = 72, 32 chunks.
__global__ __launch_bounds__(256) void conv2_gemm(const float* __restrict__ Wt, const float* __restrict__ bt,
                                                  const float* __restrict__ gammas, int l) {
    __shared__ unsigned As[128*76];
    __shared__ unsigned Hs[8*204];
    const int Kdim = CCH * 9;        // 2304
    int tid = threadIdx.x;
    int warp = tid >> 5, lane = tid & 31;
    int g = lane >> 2, l4 = lane & 3;
    int wm = warp & 1, wn = warp >> 1;
    int mbase = blockIdx.y * 128;
    int pbase = blockIdx.x * 128;
    int bimg = pbase >> 10, sbase = pbase & 1023;
    int r0 = sbase >> 5;
    const float* in0 = g_h + bimg * (CCH * SPI);

    int koffA[9], koffB[9];
#pragma unroll
    for (int ks = 0; ks < 9; ks++) {
        int k = ks*8 + l4;
        int cin = k / 9, jj = k - cin*9;
        koffA[ks] = cin*204 + (jj/3)*34 + (jj%3);
        k += 4; cin = k / 9; jj = k - cin*9;
        koffB[ks] = cin*204 + (jj/3)*34 + (jj%3);
    }
    int pixoff[4];
#pragma unroll
    for (int nt = 0; nt < 4; nt++) pixoff[nt] = wn*34 + nt*8 + g;

    float acc[4][4][4];
#pragma unroll
    for (int mt = 0; mt < 4; mt++)
#pragma unroll
        for (int nt = 0; nt < 4; nt++)
#pragma unroll
            for (int r = 0; r < 4; r++) acc[mt][nt][r] = 0.0f;

    int arow = tid >> 1, ahalf = (tid & 1) * 36;
    const float* aptr = Wt + (mbase + arow) * Kdim + ahalf;

    for (int ch = 0; ch < 32; ch++) {
        int cin0 = ch * 8;
        for (int idx = tid; idx < 1632; idx += 256) {
            int cin = idx / 204, rem = idx - cin*204;
            int rr = rem / 34, cc = rem - rr*34;
            int yy = r0 - 1 + rr, xx = cc - 1;
            float v = 0.0f;
            if (yy >= 0 && yy < HH && xx >= 0 && xx < WWW) {
                int c = cin0 + cin;
                v = fmaxf(in0[c * SPI + yy*WWW + xx] * g_scale[c] + g_shift[c], 0.0f);
            }
            Hs[idx] = f2tf(v);
        }
        const float4* ap = (const float4*)(aptr + cin0*9);
#pragma unroll
        for (int j = 0; j < 9; j++) {
            float4 v = ap[j];
            uint4 u = make_uint4(f2tf(v.x), f2tf(v.y), f2tf(v.z), f2tf(v.w));
            *(uint4*)&As[arow*76 + ahalf + j*4] = u;
        }
        __syncthreads();
#pragma unroll
        for (int ks = 0; ks < 9; ks++) {
            unsigned a[4][4], b[4][2];
#pragma unroll
            for (int mt = 0; mt < 4; mt++) {
                int r = wm*64 + mt*16 + g;
                a[mt][0] = As[r*76 + ks*8 + l4];
                a[mt][1] = As[(r+8)*76 + ks*8 + l4];
                a[mt][2] = As[r*76 + ks*8 + l4 + 4];
                a[mt][3] = As[(r+8)*76 + ks*8 + l4 + 4];
            }
#pragma unroll
            for (int nt = 0; nt < 4; nt++) {
                b[nt][0] = Hs[koffA[ks] + pixoff[nt]];
                b[nt][1] = Hs[koffB[ks] + pixoff[nt]];
            }
#pragma unroll
            for (int mt = 0; mt < 4; mt++)
#pragma unroll
                for (int nt = 0; nt < 4; nt++)
                    mma8(acc[mt][nt], a[mt], b[nt]);
        }
        __syncthreads();
    }

    // epilogue: g_x += gamma * (acc + bias)
    float gam = gammas[l];
    float* xbase = g_x + bimg * (CCH * SPI);
#pragma unroll
    for (int mt = 0; mt < 4; mt++)
#pragma unroll
        for (int half = 0; half < 2; half++) {
            int chn = mbase + wm*64 + mt*16 + g + half*8;
            float bias = bt[chn];
#pragma unroll
            for (int nt = 0; nt < 4; nt++) {
                int n = wn*32 + nt*8 + l4*2;
                float* dst = &xbase[chn * SPI + sbase + n];
                float2 old = *(float2*)dst;
                old.x += gam * (acc[mt][nt][half*2]     + bias);
                old.y += gam * (acc[mt][nt][half*2 + 1] + bias);
                *(float2*)dst = old;
            }
        }
}

// ---------------- launch ----------------
extern "C" void kernel_launch(void* const* d_in, const int* in_sizes, int n_in,
                              void* d_out, int out_size) {
    const float* x   = (const float*)d_in[0];
    const float* kw  = (const float*)d_in[1];
    const float* kb  = (const float*)d_in[2];
    const float* qw  = (const float*)d_in[3];
    const float* qb  = (const float*)d_in[4];
    const float* vw  = (const float*)d_in[5];
    const float* vb  = (const float*)d_in[6];
    const float* ow1 = (const float*)d_in[7];
    const float* ob1 = (const float*)d_in[8];
    const float* bng = (const float*)d_in[9];
    const float* bnb = (const float*)d_in[10];
    const float* ow2 = (const float*)d_in[11];
    const float* ob2 = (const float*)d_in[12];
    const float* gam = (const float*)d_in[13];

    copy_in<<<2048, 256>>>(x);
    for (int l = 0; l < NLAYERS; l++) {
        qkv_gemm<<<dim3(64, 12), 256>>>(kw + l * KHH * CCH, qw + l * KHH * CCH, vw + l * KHH * CCH,
                                        kb + l * KHH, qb + l * KHH, vb + l * KHH, l);
        attn_kernel<<<8192, 256>>>(l);
        bn_zero<<<1, 256>>>();
        conv1_gemm<<<dim3(64, 2), 256>>>(ow1 + l * CCH * KHH * 9, ob1 + l * CCH);
        bn_fin<<<1, 256>>>(bng + l * CCH, bnb + l * CCH);
        conv2_gemm<<<dim3(64, 2), 256>>>(ow2 + l * CCH * CCH * 9, ob2 + l * CCH, gam, l);
    }
    copy_out<<<2048, 256>>>((float*)d_out);
}

// round 8
// speedup vs baseline: 2.0527x; 1.0036x over previous
#include <cuda_runtime.h>

#define NLAYERS 4
#define BATCH   8
#define CCH     256
#define HH      32
#define WWW     32
#define NHEADS  8
#define DHEAD   64
#define SPI     1024
#define NPIX    8192
#define NTOK    65536
#define KHH     512

// ---------------- scratch (same set as the R2 green run) ----------------
__device__ __align__(16) float g_x[BATCH*CCH*SPI];
__device__ __align__(16) float g_keys[NLAYERS][NTOK*DHEAD];
__device__ __align__(16) float g_vals[NLAYERS][NTOK*DHEAD];
__device__ __align__(16) float g_q[NTOK*DHEAD];
__device__ __align__(16) float g_o[BATCH*KHH*SPI];
__device__ __align__(16) float g_h[BATCH*CCH*SPI];
__device__ float g_bnsum[CCH];
__device__ float g_bnsq[CCH];

// ---------------- tf32 helpers ----------------
__device__ __forceinline__ unsigned f2tf(float x) {
    unsigned r;
    asm("cvt.rna.tf32.f32 %0, %1;" : "=r"(r) : "f"(x));
    return r;
}
__device__ __forceinline__ void mma8(float (&d)[4], const unsigned (&a)[4], const unsigned (&b)[2]) {
    asm volatile(
        "mma.sync.aligned.m16n8k8.row.col.f32.tf32.tf32.f32 "
        "{%0,%1,%2,%3}, {%4,%5,%6,%7}, {%8,%9}, {%0,%1,%2,%3};"
        : "+f"(d[0]), "+f"(d[1]), "+f"(d[2]), "+f"(d[3])
        : "r"(a[0]), "r"(a[1]), "r"(a[2]), "r"(a[3]), "r"(b[0]), "r"(b[1]));
}

// ---------------- copy in/out ----------------
__global__ void copy_in(const float* __restrict__ x) {
    int i = blockIdx.x * 256 + threadIdx.x;
    ((float4*)g_x)[i] = ((const float4*)x)[i];
}
__global__ void copy_out(float* __restrict__ out) {
    int i = blockIdx.x * 256 + threadIdx.x;
    ((float4*)out)[i] = ((const float4*)g_x)[i];
}

// ---------------- QKV 1x1 conv: tf32 tensor GEMM (R2 structure) ----------------
__global__ __launch_bounds__(256) void qkv_gemm(
    const float* __restrict__ Wk, const float* __restrict__ Wq, const float* __restrict__ Wv,
    const float* __restrict__ bk, const float* __restrict__ bq, const float* __restrict__ bv,
    int l)
{
    __shared__ unsigned As[128*36];
    __shared__ unsigned Bs[32*136];
    int tid = threadIdx.x;
    int warp = tid >> 5, lane = tid & 31;
    int g = lane >> 2, l4 = lane & 3;
    int wm = warp & 1, wn = warp >> 1;
    int by = blockIdx.y, type = by >> 2, mb = by & 3;
    const float* Wt = (type == 0) ? Wk : ((type == 1) ? Wq : Wv);
    const float* bt = (type == 0) ? bk : ((type == 1) ? bq : bv);
    float* outb = (type == 0) ? g_keys[l] : ((type == 1) ? g_q : g_vals[l]);

    int pbase = blockIdx.x * 128;
    int bimg = pbase >> 10, sbase = pbase & 1023;
    const float* xin = g_x + bimg * (CCH * SPI);

    float acc[4][4][4];
#pragma unroll
    for (int mt = 0; mt < 4; mt++)
#pragma unroll
        for (int nt = 0; nt < 4; nt++)
#pragma unroll
            for (int r = 0; r < 4; r++) acc[mt][nt][r] = 0.0f;

    int arow = tid >> 1, ahalf = (tid & 1) * 16;
    int bcin = tid >> 3, bseg = (tid & 7) * 16;
    const float* aptr = Wt + (mb * 128 + arow) * CCH + ahalf;

    for (int c = 0; c < 8; c++) {
        const float4* ap = (const float4*)(aptr + c * 32);
#pragma unroll
        for (int j = 0; j < 4; j++) {
            float4 v = ap[j];
            uint4 u = make_uint4(f2tf(v.x), f2tf(v.y), f2tf(v.z), f2tf(v.w));
            *(uint4*)&As[arow*36 + ahalf + j*4] = u;
        }
        const float4* bp = (const float4*)(xin + (c*32 + bcin) * SPI + sbase + bseg);
#pragma unroll
        for (int j = 0; j < 4; j++) {
            float4 v = bp[j];
            uint4 u = make_uint4(f2tf(v.x), f2tf(v.y), f2tf(v.z), f2tf(v.w));
            *(uint4*)&Bs[bcin*136 + bseg + j*4] = u;
        }
        __syncthreads();
#pragma unroll
        for (int ks = 0; ks < 4; ks++) {
            unsigned a[4][4], b[4][2];
#pragma unroll
            for (int mt = 0; mt < 4; mt++) {
                int r = wm*64 + mt*16 + g;
                a[mt][0] = As[r*36 + ks*8 + l4];
                a[mt][1] = As[(r+8)*36 + ks*8 + l4];
                a[mt][2] = As[r*36 + ks*8 + l4 + 4];
                a[mt][3] = As[(r+8)*36 + ks*8 + l4 + 4];
            }
#pragma unroll
            for (int nt = 0; nt < 4; nt++) {
                int n = wn*32 + nt*8 + g;
                b[nt][0] = Bs[(ks*8 + l4)*136 + n];
                b[nt][1] = Bs[(ks*8 + l4 + 4)*136 + n];
            }
#pragma unroll
            for (int mt = 0; mt < 4; mt++)
#pragma unroll
                for (int nt = 0; nt < 4; nt++)
                    mma8(acc[mt][nt], a[mt], b[nt]);
        }
        __syncthreads();
    }

#pragma unroll
    for (int mt = 0; mt < 4; mt++)
#pragma unroll
        for (int half = 0; half < 2; half++) {
            int mg = mb*128 + wm*64 + mt*16 + g + half*8;
            float bias = bt[mg];
#pragma unroll
            for (int nt = 0; nt < 4; nt++) {
                int p = pbase + wn*32 + nt*8 + l4*2;
                outb[p*512 + mg]       = acc[mt][nt][half*2]     + bias;
                outb[(p+1)*512 + mg]   = acc[mt][nt][half*2 + 1] + bias;
            }
        }
}

// ---------------- attention (1 warp / token) + BN zeroing fold ----------------
__global__ __launch_bounds__(256) void attn_kernel(int l) {
    if (blockIdx.x == 0) {
        g_bnsum[threadIdx.x] = 0.0f;
        g_bnsq[threadIdx.x] = 0.0f;
    }
    int warp = threadIdx.x >> 5, lane = threadIdx.x & 31;
    int tok = blockIdx.x * 8 + warp;

    float2 q = ((const float2*)&g_q[tok * DHEAD])[lane];
    q.x *= 0.125f; q.y *= 0.125f;

    float sc[5];
#pragma unroll 4
    for (int t = 0; t <= l; t++) {
        float2 kv = ((const float2*)&g_keys[t][tok * DHEAD])[lane];
        float p = q.x * kv.x + q.y * kv.y;
#pragma unroll
        for (int o = 16; o; o >>= 1) p += __shfl_xor_sync(0xffffffffu, p, o);
        sc[t] = p;
    }
    sc[l + 1] = 0.0f;
    int T = l + 2;

    float mx = sc[0];
    for (int t = 1; t < T; t++) mx = fmaxf(mx, sc[t]);
    float e[5], sum = 0.0f;
    for (int t = 0; t < T; t++) { e[t] = expf(sc[t] - mx); sum += e[t]; }
    float inv = 1.0f / sum;
    float a[5];
    for (int t = 0; t < T; t++) a[t] = e[t] * inv;

    if (T == 5) {
        float mn1 = fminf(fminf(a[0], a[1]), fminf(fminf(a[2], a[3]), a[4]));
        float mn2 = 1e30f; bool used = false;
        for (int t = 0; t < 5; t++) {
            if (!used && a[t] == mn1) used = true;
            else mn2 = fminf(mn2, a[t]);
        }
        float delta = mn2 + 1e-7f;
        float s2 = 0.0f;
        for (int t = 0; t < 5; t++) { a[t] = fmaxf(a[t] - delta, 0.0f); s2 += a[t]; }
        float r = 1.0f / (s2 + 1e-7f);
        for (int t = 0; t < 5; t++) a[t] *= r;
    }

    float2 oacc = make_float2(0.0f, 0.0f);
#pragma unroll 4
    for (int t = 0; t <= l; t++) {
        float2 vv = ((const float2*)&g_vals[t][tok * DHEAD])[lane];
        oacc.x += a[t] * vv.x;
        oacc.y += a[t] * vv.y;
    }

    int p = tok >> 3, head = tok & 7;
    int bimg = p >> 10, s = p & 1023;
    float* op = g_o + bimg * (KHH * SPI) + (head * DHEAD + lane * 2) * SPI + s;
    op[0]   = oacc.x;
    op[SPI] = oacc.y;
}

// ---------------- conv1: 3x3, 512->256 (R2 structure, BN stats in epilogue) ----
__global__ __launch_bounds__(256) void conv1_gemm(const float* __restrict__ Wt, const float* __restrict__ bt) {
    __shared__ unsigned As[128*76];
    __shared__ unsigned Hs[8*204];
    const int Kdim = KHH * 9;
    int tid = threadIdx.x;
    int warp = tid >> 5, lane = tid & 31;
    int g = lane >> 2, l4 = lane & 3;
    int wm = warp & 1, wn = warp >> 1;
    int mbase = blockIdx.y * 128;
    int pbase = blockIdx.x * 128;
    int bimg = pbase >> 10, sbase = pbase & 1023;
    int r0 = sbase >> 5;
    const float* in0 = g_o + bimg * (KHH * SPI);

    int koffA[9], koffB[9];
#pragma unroll
    for (int ks = 0; ks < 9; ks++) {
        int k = ks*8 + l4;
        int cin = k / 9, jj = k - cin*9;
        koffA[ks] = cin*204 + (jj/3)*34 + (jj%3);
        k += 4; cin = k / 9; jj = k - cin*9;
        koffB[ks] = cin*204 + (jj/3)*34 + (jj%3);
    }
    int pixoff[4];
#pragma unroll
    for (int nt = 0; nt < 4; nt++) pixoff[nt] = wn*34 + nt*8 + g;

    float acc[4][4][4];
#pragma unroll
    for (int mt = 0; mt < 4; mt++)
#pragma unroll
        for (int nt = 0; nt < 4; nt++)
#pragma unroll
            for (int r = 0; r < 4; r++) acc[mt][nt][r] = 0.0f;

    int arow = tid >> 1, ahalf = (tid & 1) * 36;
    const float* aptr = Wt + (mbase + arow) * Kdim + ahalf;

    for (int ch = 0; ch < 64; ch++) {
        int cin0 = ch * 8;
        for (int idx = tid; idx < 1632; idx += 256) {
            int cin = idx / 204, rem = idx - cin*204;
            int rr = rem / 34, cc = rem - rr*34;
            int yy = r0 - 1 + rr, xx = cc - 1;
            float v = 0.0f;
            if (yy >= 0 && yy < HH && xx >= 0 && xx < WWW)
                v = in0[(cin0 + cin) * SPI + yy*WWW + xx];
            Hs[idx] = f2tf(v);
        }
        const float4* ap = (const float4*)(aptr + cin0*9);
#pragma unroll
        for (int j = 0; j < 9; j++) {
            float4 v = ap[j];
            uint4 u = make_uint4(f2tf(v.x), f2tf(v.y), f2tf(v.z), f2tf(v.w));
            *(uint4*)&As[arow*76 + ahalf + j*4] = u;
        }
        __syncthreads();
#pragma unroll
        for (int ks = 0; ks < 9; ks++) {
            unsigned a[4][4], b[4][2];
#pragma unroll
            for (int mt = 0; mt < 4; mt++) {
                int r = wm*64 + mt*16 + g;
                a[mt][0] = As[r*76 + ks*8 + l4];
                a[mt][1] = As[(r+8)*76 + ks*8 + l4];
                a[mt][2] = As[r*76 + ks*8 + l4 + 4];
                a[mt][3] = As[(r+8)*76 + ks*8 + l4 + 4];
            }
#pragma unroll
            for (int nt = 0; nt < 4; nt++) {
                b[nt][0] = Hs[koffA[ks] + pixoff[nt]];
                b[nt][1] = Hs[koffB[ks] + pixoff[nt]];
            }
#pragma unroll
            for (int mt = 0; mt < 4; mt++)
#pragma unroll
                for (int nt = 0; nt < 4; nt++)
                    mma8(acc[mt][nt], a[mt], b[nt]);
        }
        __syncthreads();
    }

    float* hbase = g_h + bimg * (CCH * SPI);
#pragma unroll
    for (int mt = 0; mt < 4; mt++)
#pragma unroll
        for (int half = 0; half < 2; half++) {
            int chn = mbase + wm*64 + mt*16 + g + half*8;
            float bias = bt[chn];
            float s = 0.0f, qq = 0.0f;
#pragma unroll
            for (int nt = 0; nt < 4; nt++) {
                float v0 = acc[mt][nt][half*2]     + bias;
                float v1 = acc[mt][nt][half*2 + 1] + bias;
                int n = wn*32 + nt*8 + l4*2;
                *(float2*)&hbase[chn * SPI + sbase + n] = make_float2(v0, v1);
                s += v0 + v1;
                qq += v0*v0 + v1*v1;
            }
            s  += __shfl_xor_sync(0xffffffffu, s, 1);
            s  += __shfl_xor_sync(0xffffffffu, s, 2);
            qq += __shfl_xor_sync(0xffffffffu, qq, 1);
            qq += __shfl_xor_sync(0xffffffffu, qq, 2);
            if (l4 == 0) {
                atomicAdd(&g_bnsum[chn], s);
                atomicAdd(&g_bnsq[chn], qq);
            }
        }
}

// ---------------- conv2: 3x3, 256->256; BN finalize folded into prologue -------
__global__ __launch_bounds__(256) void conv2_gemm(const float* __restrict__ Wt, const float* __restrict__ bt,
                                                  const float* __restrict__ bng, const float* __restrict__ bnb,
                                                  const float* __restrict__ gammas, int l) {
    __shared__ unsigned As[128*76];
    __shared__ unsigned Hs[8*204];
    __shared__ float s_scale[CCH];
    __shared__ float s_shift[CCH];
    const int Kdim = CCH * 9;
    int tid = threadIdx.x;
    int warp = tid >> 5, lane = tid & 31;
    int g = lane >> 2, l4 = lane & 3;
    int wm = warp & 1, wn = warp >> 1;
    int mbase = blockIdx.y * 128;
    int pbase = blockIdx.x * 128;
    int bimg = pbase >> 10, sbase = pbase & 1023;
    int r0 = sbase >> 5;
    const float* in0 = g_h + bimg * (CCH * SPI);

    // BN finalize (each CTA redundantly; deterministic)
    {
        float m = g_bnsum[tid] * (1.0f / (float)NPIX);
        float v = g_bnsq[tid] * (1.0f / (float)NPIX) - m * m;
        float sc = bng[tid] * rsqrtf(v + 1e-5f);
        s_scale[tid] = sc;
        s_shift[tid] = bnb[tid] - m * sc;
    }
    __syncthreads();

    int koffA[9], koffB[9];
#pragma unroll
    for (int ks = 0; ks < 9; ks++) {
        int k = ks*8 + l4;
        int cin = k / 9, jj = k - cin*9;
        koffA[ks] = cin*204 + (jj/3)*34 + (jj%3);
        k += 4; cin = k / 9; jj = k - cin*9;
        koffB[ks] = cin*204 + (jj/3)*34 + (jj%3);
    }
    int pixoff[4];
#pragma unroll
    for (int nt = 0; nt < 4; nt++) pixoff[nt] = wn*34 + nt*8 + g;

    float acc[4][4][4];
#pragma unroll
    for (int mt = 0; mt < 4; mt++)
#pragma unroll
        for (int nt = 0; nt < 4; nt++)
#pragma unroll
            for (int r = 0; r < 4; r++) acc[mt][nt][r] = 0.0f;

    int arow = tid >> 1, ahalf = (tid & 1) * 36;
    const float* aptr = Wt + (mbase + arow) * Kdim + ahalf;

    for (int ch = 0; ch < 32; ch++) {
        int cin0 = ch * 8;
        for (int idx = tid; idx < 1632; idx += 256) {
            int cin = idx / 204, rem = idx - cin*204;
            int rr = rem / 34, cc = rem - rr*34;
            int yy = r0 - 1 + rr, xx = cc - 1;
            float v = 0.0f;
            if (yy >= 0 && yy < HH && xx >= 0 && xx < WWW) {
                int c = cin0 + cin;
                v = fmaxf(in0[c * SPI + yy*WWW + xx] * s_scale[c] + s_shift[c], 0.0f);
            }
            Hs[idx] = f2tf(v);
        }
        const float4* ap = (const float4*)(aptr + cin0*9);
#pragma unroll
        for (int j = 0; j < 9; j++) {
            float4 v = ap[j];
            uint4 u = make_uint4(f2tf(v.x), f2tf(v.y), f2tf(v.z), f2tf(v.w));
            *(uint4*)&As[arow*76 + ahalf + j*4] = u;
        }
        __syncthreads();
#pragma unroll
        for (int ks = 0; ks < 9; ks++) {
            unsigned a[4][4], b[4][2];
#pragma unroll
            for (int mt = 0; mt < 4; mt++) {
                int r = wm*64 + mt*16 + g;
                a[mt][0] = As[r*76 + ks*8 + l4];
                a[mt][1] = As[(r+8)*76 + ks*8 + l4];
                a[mt][2] = As[r*76 + ks*8 + l4 + 4];
                a[mt][3] = As[(r+8)*76 + ks*8 + l4 + 4];
            }
#pragma unroll
            for (int nt = 0; nt < 4; nt++) {
                b[nt][0] = Hs[koffA[ks] + pixoff[nt]];
                b[nt][1] = Hs[koffB[ks] + pixoff[nt]];
            }
#pragma unroll
            for (int mt = 0; mt < 4; mt++)
#pragma unroll
                for (int nt = 0; nt < 4; nt++)
                    mma8(acc[mt][nt], a[mt], b[nt]);
        }
        __syncthreads();
    }

    float gam = gammas[l];
    float* xbase = g_x + bimg * (CCH * SPI);
#pragma unroll
    for (int mt = 0; mt < 4; mt++)
#pragma unroll
        for (int half = 0; half < 2; half++) {
            int chn = mbase + wm*64 + mt*16 + g + half*8;
            float bias = bt[chn];
#pragma unroll
            for (int nt = 0; nt < 4; nt++) {
                int n = wn*32 + nt*8 + l4*2;
                float* dst = &xbase[chn * SPI + sbase + n];
                float2 old = *(float2*)dst;
                old.x += gam * (acc[mt][nt][half*2]     + bias);
                old.y += gam * (acc[mt][nt][half*2 + 1] + bias);
                *(float2*)dst = old;
            }
        }
}

// ---------------- launch ----------------
extern "C" void kernel_launch(void* const* d_in, const int* in_sizes, int n_in,
                              void* d_out, int out_size) {
    const float* x   = (const float*)d_in[0];
    const float* kw  = (const float*)d_in[1];
    const float* kb  = (const float*)d_in[2];
    const float* qw  = (const float*)d_in[3];
    const float* qb  = (const float*)d_in[4];
    const float* vw  = (const float*)d_in[5];
    const float* vb  = (const float*)d_in[6];
    const float* ow1 = (const float*)d_in[7];
    const float* ob1 = (const float*)d_in[8];
    const float* bng = (const float*)d_in[9];
    const float* bnb = (const float*)d_in[10];
    const float* ow2 = (const float*)d_in[11];
    const float* ob2 = (const float*)d_in[12];
    const float* gam = (const float*)d_in[13];

    copy_in<<<2048, 256>>>(x);
    for (int l = 0; l < NLAYERS; l++) {
        qkv_gemm<<<dim3(64, 12), 256>>>(kw + l * KHH * CCH, qw + l * KHH * CCH, vw + l * KHH * CCH,
                                        kb + l * KHH, qb + l * KHH, vb + l * KHH, l);
        attn_kernel<<<8192, 256>>>(l);
        conv1_gemm<<<dim3(64, 2), 256>>>(ow1 + l * CCH * KHH * 9, ob1 + l * CCH);
        conv2_gemm<<<dim3(64, 2), 256>>>(ow2 + l * CCH * CCH * 9, ob2 + l * CCH,
                                         bng + l * CCH, bnb + l * CCH, gam, l);
    }
    copy_out<<<2048, 256>>>((float*)d_out);
}

// round 9
// speedup vs baseline: 2.1225x; 1.0340x over previous
#include <cuda_runtime.h>

#define NLAYERS 4
#define BATCH   8
#define CCH     256
#define HH      32
#define WWW     32
#define NHEADS  8
#define DHEAD   64
#define SPI     1024
#define NPIX    8192
#define NTOK    65536
#define KHH     512

// ---------------- scratch (EXACT same set as green R8 run; no new globals) ----
__device__ __align__(16) float g_x[BATCH*CCH*SPI];
__device__ __align__(16) float g_keys[NLAYERS][NTOK*DHEAD];
__device__ __align__(16) float g_vals[NLAYERS][NTOK*DHEAD];
__device__ __align__(16) float g_q[NTOK*DHEAD];     // doubles as conv weight-frag scratch
__device__ __align__(16) float g_o[BATCH*KHH*SPI];
__device__ __align__(16) float g_h[BATCH*CCH*SPI];  // doubles as qkv weight-frag scratch
__device__ float g_bnsum[CCH];
__device__ float g_bnsq[CCH];

// overlay offsets (uint elements)
#define QKV_FRAG_SZ   131072      // 512*256 per matrix
#define C1_FRAG_OFF   0           // in g_q
#define C2_FRAG_OFF   1179648     // 256*4608, then 256*2304 follows

// ---------------- tf32 helpers ----------------
__device__ __forceinline__ unsigned f2tf(float x) {
    unsigned r;
    asm("cvt.rna.tf32.f32 %0, %1;" : "=r"(r) : "f"(x));
    return r;
}
__device__ __forceinline__ void mma8v(float (&d)[4], uint4 a, unsigned b0, unsigned b1) {
    asm volatile(
        "mma.sync.aligned.m16n8k8.row.col.f32.tf32.tf32.f32 "
        "{%0,%1,%2,%3}, {%4,%5,%6,%7}, {%8,%9}, {%0,%1,%2,%3};"
        : "+f"(d[0]), "+f"(d[1]), "+f"(d[2]), "+f"(d[3])
        : "r"(a.x), "r"(a.y), "r"(a.z), "r"(a.w), "r"(b0), "r"(b1));
}

// ---------------- weight conversion into existing scratch (no new globals) ----
// frag layout idx = (((ch*KS + ks)*NMT + mt)*32 + lane)*4 + reg
__global__ void wconv(const float* __restrict__ W, int dstSel, int dstOff,
                      int Kdim, int CK, int NMT) {
    unsigned* Wc = (dstSel ? (unsigned*)g_q : (unsigned*)g_h) + dstOff;
    int idx = blockIdx.x * 256 + threadIdx.x;
    int m = idx / Kdim, k = idx - m * Kdim;
    int ch = k / CK, kc = k - ch * CK;
    int ks = kc >> 3, c = kc & 7;
    int KS = CK >> 3;
    int mt = m >> 4, rr = m & 15, gg = rr & 7;
    int lane = gg * 4 + (c & 3);
    int reg = (rr >> 3) + ((c >> 2) << 1);
    Wc[(((ch*KS + ks)*NMT + mt)*32 + lane)*4 + reg] = f2tf(W[idx]);
}

// ---------------- copy in/out ----------------
__global__ void copy_in(const float* __restrict__ x) {
    int i = blockIdx.x * 256 + threadIdx.x;
    ((float4*)g_x)[i] = ((const float4*)x)[i];
}
__global__ void copy_out(float* __restrict__ out) {
    int i = blockIdx.x * 256 + threadIdx.x;
    ((float4*)out)[i] = ((const float4*)g_x)[i];
}

// ---------------- QKV 1x1 conv: A from pre-converted frags in g_h ----------------
__global__ __launch_bounds__(256) void qkv_gemm(
    const float* __restrict__ bk, const float* __restrict__ bq, const float* __restrict__ bv,
    int l)
{
    __shared__ unsigned Bs[32*136];
    int tid = threadIdx.x;
    int warp = tid >> 5, lane = tid & 31;
    int g = lane >> 2, l4 = lane & 3;
    int wm = warp & 1, wn = warp >> 1;
    int by = blockIdx.y, type = by >> 2, mb = by & 3;
    const float* bt = (type == 0) ? bk : ((type == 1) ? bq : bv);
    float* outb = (type == 0) ? g_keys[l] : ((type == 1) ? g_q : g_vals[l]);
    const uint4* Ab = (const uint4*)((const unsigned*)g_h + type * QKV_FRAG_SZ);

    int pbase = blockIdx.x * 128;
    int bimg = pbase >> 10, sbase = pbase & 1023;
    const float* xin = g_x + bimg * (CCH * SPI);

    float acc[4][4][4];
#pragma unroll
    for (int mt = 0; mt < 4; mt++)
#pragma unroll
        for (int nt = 0; nt < 4; nt++)
#pragma unroll
            for (int r = 0; r < 4; r++) acc[mt][nt][r] = 0.0f;

    int bcin = tid >> 3, bseg = (tid & 7) * 16;

    for (int c = 0; c < 8; c++) {
        const float4* bp = (const float4*)(xin + (c*32 + bcin) * SPI + sbase + bseg);
#pragma unroll
        for (int j = 0; j < 4; j++) {
            float4 v = bp[j];
            uint4 u = make_uint4(f2tf(v.x), f2tf(v.y), f2tf(v.z), f2tf(v.w));
            *(uint4*)&Bs[bcin*136 + bseg + j*4] = u;
        }
        __syncthreads();
#pragma unroll
        for (int ks = 0; ks < 4; ks++) {
            int abase = ((c*4 + ks)*32 + mb*8 + wm*4)*32 + lane;
            uint4 af[4];
#pragma unroll
            for (int mt = 0; mt < 4; mt++) af[mt] = Ab[abase + mt*32];
            unsigned b[4][2];
#pragma unroll
            for (int nt = 0; nt < 4; nt++) {
                int n = wn*32 + nt*8 + g;
                b[nt][0] = Bs[(ks*8 + l4)*136 + n];
                b[nt][1] = Bs[(ks*8 + l4 + 4)*136 + n];
            }
#pragma unroll
            for (int mt = 0; mt < 4; mt++)
#pragma unroll
                for (int nt = 0; nt < 4; nt++)
                    mma8v(acc[mt][nt], af[mt], b[nt][0], b[nt][1]);
        }
        __syncthreads();
    }

#pragma unroll
    for (int mt = 0; mt < 4; mt++)
#pragma unroll
        for (int half = 0; half < 2; half++) {
            int mg = mb*128 + wm*64 + mt*16 + g + half*8;
            float bias = bt[mg];
#pragma unroll
            for (int nt = 0; nt < 4; nt++) {
                int p = pbase + wn*32 + nt*8 + l4*2;
                outb[p*512 + mg]       = acc[mt][nt][half*2]     + bias;
                outb[(p+1)*512 + mg]   = acc[mt][nt][half*2 + 1] + bias;
            }
        }
}

// ---------------- attention (1 warp / token) + BN zeroing fold ----------------
__global__ __launch_bounds__(256) void attn_kernel(int l) {
    if (blockIdx.x == 0) {
        g_bnsum[threadIdx.x] = 0.0f;
        g_bnsq[threadIdx.x] = 0.0f;
    }
    int warp = threadIdx.x >> 5, lane = threadIdx.x & 31;
    int tok = blockIdx.x * 8 + warp;

    float2 q = ((const float2*)&g_q[tok * DHEAD])[lane];
    q.x *= 0.125f; q.y *= 0.125f;

    float sc[5];
#pragma unroll 4
    for (int t = 0; t <= l; t++) {
        float2 kv = ((const float2*)&g_keys[t][tok * DHEAD])[lane];
        float p = q.x * kv.x + q.y * kv.y;
#pragma unroll
        for (int o = 16; o; o >>= 1) p += __shfl_xor_sync(0xffffffffu, p, o);
        sc[t] = p;
    }
    sc[l + 1] = 0.0f;
    int T = l + 2;

    float mx = sc[0];
    for (int t = 1; t < T; t++) mx = fmaxf(mx, sc[t]);
    float e[5], sum = 0.0f;
    for (int t = 0; t < T; t++) { e[t] = expf(sc[t] - mx); sum += e[t]; }
    float inv = 1.0f / sum;
    float a[5];
    for (int t = 0; t < T; t++) a[t] = e[t] * inv;

    if (T == 5) {
        float mn1 = fminf(fminf(a[0], a[1]), fminf(fminf(a[2], a[3]), a[4]));
        float mn2 = 1e30f; bool used = false;
        for (int t = 0; t < 5; t++) {
            if (!used && a[t] == mn1) used = true;
            else mn2 = fminf(mn2, a[t]);
        }
        float delta = mn2 + 1e-7f;
        float s2 = 0.0f;
        for (int t = 0; t < 5; t++) { a[t] = fmaxf(a[t] - delta, 0.0f); s2 += a[t]; }
        float r = 1.0f / (s2 + 1e-7f);
        for (int t = 0; t < 5; t++) a[t] *= r;
    }

    float2 oacc = make_float2(0.0f, 0.0f);
#pragma unroll 4
    for (int t = 0; t <= l; t++) {
        float2 vv = ((const float2*)&g_vals[t][tok * DHEAD])[lane];
        oacc.x += a[t] * vv.x;
        oacc.y += a[t] * vv.y;
    }

    int p = tok >> 3, head = tok & 7;
    int bimg = p >> 10, s = p & 1023;
    float* op = g_o + bimg * (KHH * SPI) + (head * DHEAD + lane * 2) * SPI + s;
    op[0]   = oacc.x;
    op[SPI] = oacc.y;
}

// ---------------- conv1: 3x3, 512->256; A frags from g_q; halo B in smem -------
__global__ __launch_bounds__(256) void conv1_gemm(const float* __restrict__ bt) {
    __shared__ unsigned Hs[8*204];
    int tid = threadIdx.x;
    int warp = tid >> 5, lane = tid & 31;
    int g = lane >> 2, l4 = lane & 3;
    int wm = warp & 1, wn = warp >> 1;
    int mbase = blockIdx.y * 128;
    int pbase = blockIdx.x * 128;
    int bimg = pbase >> 10, sbase = pbase & 1023;
    int r0 = sbase >> 5;
    const float* in0 = g_o + bimg * (KHH * SPI);
    const uint4* Ab = (const uint4*)((const unsigned*)g_q + C1_FRAG_OFF);
    int mtb = blockIdx.y * 8;

    int koffA[9], koffB[9];
#pragma unroll
    for (int ks = 0; ks < 9; ks++) {
        int k = ks*8 + l4;
        int cin = k / 9, jj = k - cin*9;
        koffA[ks] = cin*204 + (jj/3)*34 + (jj%3);
        k += 4; cin = k / 9; jj = k - cin*9;
        koffB[ks] = cin*204 + (jj/3)*34 + (jj%3);
    }
    int pixoff[4];
#pragma unroll
    for (int nt = 0; nt < 4; nt++) pixoff[nt] = wn*34 + nt*8 + g;

    float acc[4][4][4];
#pragma unroll
    for (int mt = 0; mt < 4; mt++)
#pragma unroll
        for (int nt = 0; nt < 4; nt++)
#pragma unroll
            for (int r = 0; r < 4; r++) acc[mt][nt][r] = 0.0f;

    for (int ch = 0; ch < 64; ch++) {
        int cin0 = ch * 8;
        for (int idx = tid; idx < 1632; idx += 256) {
            int cin = idx / 204, rem = idx - cin*204;
            int rr = rem / 34, cc = rem - rr*34;
            int yy = r0 - 1 + rr, xx = cc - 1;
            float v = 0.0f;
            if (yy >= 0 && yy < HH && xx >= 0 && xx < WWW)
                v = in0[(cin0 + cin) * SPI + yy*WWW + xx];
            Hs[idx] = f2tf(v);
        }
        __syncthreads();
#pragma unroll
        for (int ks = 0; ks < 9; ks++) {
            int abase = ((ch*9 + ks)*16 + mtb + wm*4)*32 + lane;
            uint4 af[4];
#pragma unroll
            for (int mt = 0; mt < 4; mt++) af[mt] = Ab[abase + mt*32];
            unsigned b[4][2];
#pragma unroll
            for (int nt = 0; nt < 4; nt++) {
                b[nt][0] = Hs[koffA[ks] + pixoff[nt]];
                b[nt][1] = Hs[koffB[ks] + pixoff[nt]];
            }
#pragma unroll
            for (int mt = 0; mt < 4; mt++)
#pragma unroll
                for (int nt = 0; nt < 4; nt++)
                    mma8v(acc[mt][nt], af[mt], b[nt][0], b[nt][1]);
        }
        __syncthreads();
    }

    float* hbase = g_h + bimg * (CCH * SPI);
#pragma unroll
    for (int mt = 0; mt < 4; mt++)
#pragma unroll
        for (int half = 0; half < 2; half++) {
            int chn = mbase + wm*64 + mt*16 + g + half*8;
            float bias = bt[chn];
            float s = 0.0f, qq = 0.0f;
#pragma unroll
            for (int nt = 0; nt < 4; nt++) {
                float v0 = acc[mt][nt][half*2]     + bias;
                float v1 = acc[mt][nt][half*2 + 1] + bias;
                int n = wn*32 + nt*8 + l4*2;
                *(float2*)&hbase[chn * SPI + sbase + n] = make_float2(v0, v1);
                s += v0 + v1;
                qq += v0*v0 + v1*v1;
            }
            s  += __shfl_xor_sync(0xffffffffu, s, 1);
            s  += __shfl_xor_sync(0xffffffffu, s, 2);
            qq += __shfl_xor_sync(0xffffffffu, qq, 1);
            qq += __shfl_xor_sync(0xffffffffu, qq, 2);
            if (l4 == 0) {
                atomicAdd(&g_bnsum[chn], s);
                atomicAdd(&g_bnsq[chn], qq);
            }
        }
}

// ---------------- conv2: A frags from g_q+off; BN finalize+apply+ReLU; residual -
__global__ __launch_bounds__(256) void conv2_gemm(const float* __restrict__ bt,
                                                  const float* __restrict__ bng, const float* __restrict__ bnb,
                                                  const float* __restrict__ gammas, int l) {
    __shared__ unsigned Hs[8*204];
    __shared__ float s_scale[CCH];
    __shared__ float s_shift[CCH];
    int tid = threadIdx.x;
    int warp = tid >> 5, lane = tid & 31;
    int g = lane >> 2, l4 = lane & 3;
    int wm = warp & 1, wn = warp >> 1;
    int mbase = blockIdx.y * 128;
    int pbase = blockIdx.x * 128;
    int bimg = pbase >> 10, sbase = pbase & 1023;
    int r0 = sbase >> 5;
    const float* in0 = g_h + bimg * (CCH * SPI);
    const uint4* Ab = (const uint4*)((const unsigned*)g_q + C2_FRAG_OFF);
    int mtb = blockIdx.y * 8;

    {
        float m = g_bnsum[tid] * (1.0f / (float)NPIX);
        float v = g_bnsq[tid] * (1.0f / (float)NPIX) - m * m;
        float sc = bng[tid] * rsqrtf(v + 1e-5f);
        s_scale[tid] = sc;
        s_shift[tid] = bnb[tid] - m * sc;
    }
    __syncthreads();

    int koffA[9], koffB[9];
#pragma unroll
    for (int ks = 0; ks < 9; ks++) {
        int k = ks*8 + l4;
        int cin = k / 9, jj = k - cin*9;
        koffA[ks] = cin*204 + (jj/3)*34 + (jj%3);
        k += 4; cin = k / 9; jj = k - cin*9;
        koffB[ks] = cin*204 + (jj/3)*34 + (jj%3);
    }
    int pixoff[4];
#pragma unroll
    for (int nt = 0; nt < 4; nt++) pixoff[nt] = wn*34 + nt*8 + g;

    float acc[4][4][4];
#pragma unroll
    for (int mt = 0; mt < 4; mt++)
#pragma unroll
        for (int nt = 0; nt < 4; nt++)
#pragma unroll
            for (int r = 0; r < 4; r++) acc[mt][nt][r] = 0.0f;

    for (int ch = 0; ch < 32; ch++) {
        int cin0 = ch * 8;
        for (int idx = tid; idx < 1632; idx += 256) {
            int cin = idx / 204, rem = idx - cin*204;
            int rr = rem / 34, cc = rem - rr*34;
            int yy = r0 - 1 + rr, xx = cc - 1;
            float v = 0.0f;
            if (yy >= 0 && yy < HH && xx >= 0 && xx < WWW) {
                int c = cin0 + cin;
                v = fmaxf(in0[c * SPI + yy*WWW + xx] * s_scale[c] + s_shift[c], 0.0f);
            }
            Hs[idx] = f2tf(v);
        }
        __syncthreads();
#pragma unroll
        for (int ks = 0; ks < 9; ks++) {
            int abase = ((ch*9 + ks)*16 + mtb + wm*4)*32 + lane;
            uint4 af[4];
#pragma unroll
            for (int mt = 0; mt < 4; mt++) af[mt] = Ab[abase + mt*32];
            unsigned b[4][2];
#pragma unroll
            for (int nt = 0; nt < 4; nt++) {
                b[nt][0] = Hs[koffA[ks] + pixoff[nt]];
                b[nt][1] = Hs[koffB[ks] + pixoff[nt]];
            }
#pragma unroll
            for (int mt = 0; mt < 4; mt++)
#pragma unroll
                for (int nt = 0; nt < 4; nt++)
                    mma8v(acc[mt][nt], af[mt], b[nt][0], b[nt][1]);
        }
        __syncthreads();
    }

    float gam = gammas[l];
    float* xbase = g_x + bimg * (CCH * SPI);
#pragma unroll
    for (int mt = 0; mt < 4; mt++)
#pragma unroll
        for (int half = 0; half < 2; half++) {
            int chn = mbase + wm*64 + mt*16 + g + half*8;
            float bias = bt[chn];
#pragma unroll
            for (int nt = 0; nt < 4; nt++) {
                int n = wn*32 + nt*8 + l4*2;
                float* dst = &xbase[chn * SPI + sbase + n];
                float2 old = *(float2*)dst;
                old.x += gam * (acc[mt][nt][half*2]     + bias);
                old.y += gam * (acc[mt][nt][half*2 + 1] + bias);
                *(float2*)dst = old;
            }
        }
}

// ---------------- launch ----------------
extern "C" void kernel_launch(void* const* d_in, const int* in_sizes, int n_in,
                              void* d_out, int out_size) {
    const float* x   = (const float*)d_in[0];
    const float* kw  = (const float*)d_in[1];
    const float* kb  = (const float*)d_in[2];
    const float* qw  = (const float*)d_in[3];
    const float* qb  = (const float*)d_in[4];
    const float* vw  = (const float*)d_in[5];
    const float* vb  = (const float*)d_in[6];
    const float* ow1 = (const float*)d_in[7];
    const float* ob1 = (const float*)d_in[8];
    const float* bng = (const float*)d_in[9];
    const float* bnb = (const float*)d_in[10];
    const float* ow2 = (const float*)d_in[11];
    const float* ob2 = (const float*)d_in[12];
    const float* gam = (const float*)d_in[13];

    copy_in<<<2048, 256>>>(x);
    for (int l = 0; l < NLAYERS; l++) {
        // qkv weight frags -> g_h (dead until conv1 writes it)
        wconv<<<512, 256>>>(kw + l*KHH*CCH, 0, 0,              256, 32, 32);
        wconv<<<512, 256>>>(qw + l*KHH*CCH, 0, QKV_FRAG_SZ,    256, 32, 32);
        wconv<<<512, 256>>>(vw + l*KHH*CCH, 0, 2*QKV_FRAG_SZ,  256, 32, 32);
        qkv_gemm<<<dim3(64, 12), 256>>>(kb + l*KHH, qb + l*KHH, vb + l*KHH, l);
        attn_kernel<<<8192, 256>>>(l);
        // conv weight frags -> g_q (dead after attn consumed it)
        wconv<<<4608, 256>>>(ow1 + l*CCH*KHH*9, 1, C1_FRAG_OFF, 4608, 72, 16);
        wconv<<<2304, 256>>>(ow2 + l*CCH*CCH*9, 1, C2_FRAG_OFF, 2304, 72, 16);
        conv1_gemm<<<dim3(64, 2), 256>>>(ob1 + l*CCH);
        conv2_gemm<<<dim3(64, 2), 256>>>(ob2 + l*CCH, bng + l*CCH, bnb + l*CCH, gam, l);
    }
    copy_out<<<2048, 256>>>((float*)d_out);
}

// round 10
// speedup vs baseline: 3.0238x; 1.4247x over previous
#include <cuda_runtime.h>

#define NLAYERS 4
#define BATCH   8
#define CCH     256
#define HH      32
#define WWW     32
#define NHEADS  8
#define DHEAD   64
#define SPI     1024
#define NPIX    8192
#define NTOK    65536
#define KHH     512

// ---------------- scratch (EXACT same set as green R9 run; no new globals) ----
__device__ __align__(16) float g_x[BATCH*CCH*SPI];
__device__ __align__(16) float g_keys[NLAYERS][NTOK*DHEAD];
__device__ __align__(16) float g_vals[NLAYERS][NTOK*DHEAD];
__device__ __align__(16) float g_q[NTOK*DHEAD];     // doubles as conv weight-frag scratch
__device__ __align__(16) float g_o[BATCH*KHH*SPI];
__device__ __align__(16) float g_h[BATCH*CCH*SPI];  // doubles as qkv weight-frag scratch
__device__ float g_bnsum[CCH];
__device__ float g_bnsq[CCH];

// overlay offsets (uint elements)
#define QKV_FRAG_SZ   131072      // 512*256 per matrix
#define C1_FRAG_OFF   0           // in g_q
#define C2_FRAG_OFF   1179648     // 256*4608, then 256*2304 follows

// ---------------- tf32 helpers ----------------
__device__ __forceinline__ unsigned f2tf(float x) {
    unsigned r;
    asm("cvt.rna.tf32.f32 %0, %1;" : "=r"(r) : "f"(x));
    return r;
}
__device__ __forceinline__ void mma8v(float (&d)[4], uint4 a, unsigned b0, unsigned b1) {
    asm volatile(
        "mma.sync.aligned.m16n8k8.row.col.f32.tf32.tf32.f32 "
        "{%0,%1,%2,%3}, {%4,%5,%6,%7}, {%8,%9}, {%0,%1,%2,%3};"
        : "+f"(d[0]), "+f"(d[1]), "+f"(d[2]), "+f"(d[3])
        : "r"(a.x), "r"(a.y), "r"(a.z), "r"(a.w), "r"(b0), "r"(b1));
}

// ---------------- weight conversion into existing scratch (no new globals) ----
// frag layout idx = (((ch*KS + ks)*NMT + mt)*32 + lane)*4 + reg
__global__ void wconv(const float* __restrict__ W, int dstSel, int dstOff,
                      int Kdim, int CK, int NMT) {
    unsigned* Wc = (dstSel ? (unsigned*)g_q : (unsigned*)g_h) + dstOff;
    int idx = blockIdx.x * 256 + threadIdx.x;
    int m = idx / Kdim, k = idx - m * Kdim;
    int ch = k / CK, kc = k - ch * CK;
    int ks = kc >> 3, c = kc & 7;
    int KS = CK >> 3;
    int mt = m >> 4, rr = m & 15, gg = rr & 7;
    int lane = gg * 4 + (c & 3);
    int reg = (rr >> 3) + ((c >> 2) << 1);
    Wc[(((ch*KS + ks)*NMT + mt)*32 + lane)*4 + reg] = f2tf(W[idx]);
}

// ---------------- copy in/out ----------------
__global__ void copy_in(const float* __restrict__ x) {
    int i = blockIdx.x * 256 + threadIdx.x;
    ((float4*)g_x)[i] = ((const float4*)x)[i];
}
__global__ void copy_out(float* __restrict__ out) {
    int i = blockIdx.x * 256 + threadIdx.x;
    ((float4*)out)[i] = ((const float4*)g_x)[i];
}

// ---------------- QKV 1x1 conv: A from frags in g_h; B chunk prefetched --------
__global__ __launch_bounds__(256) void qkv_gemm(
    const float* __restrict__ bk, const float* __restrict__ bq, const float* __restrict__ bv,
    int l)
{
    __shared__ unsigned Bs[32*136];
    int tid = threadIdx.x;
    int warp = tid >> 5, lane = tid & 31;
    int g = lane >> 2, l4 = lane & 3;
    int wm = warp & 1, wn = warp >> 1;
    int by = blockIdx.y, type = by >> 2, mb = by & 3;
    const float* bt = (type == 0) ? bk : ((type == 1) ? bq : bv);
    float* outb = (type == 0) ? g_keys[l] : ((type == 1) ? g_q : g_vals[l]);
    const uint4* Ab = (const uint4*)((const unsigned*)g_h + type * QKV_FRAG_SZ);

    int pbase = blockIdx.x * 128;
    int bimg = pbase >> 10, sbase = pbase & 1023;
    const float* xin = g_x + bimg * (CCH * SPI);

    float acc[4][4][4];
#pragma unroll
    for (int mt = 0; mt < 4; mt++)
#pragma unroll
        for (int nt = 0; nt < 4; nt++)
#pragma unroll
            for (int r = 0; r < 4; r++) acc[mt][nt][r] = 0.0f;

    int bcin = tid >> 3, bseg = (tid & 7) * 16;
    const float* bbase = xin + bcin * SPI + sbase + bseg;

    float4 pb[4];
    {
        const float4* bp = (const float4*)bbase;
#pragma unroll
        for (int j = 0; j < 4; j++) pb[j] = bp[j];
    }

    for (int c = 0; c < 8; c++) {
#pragma unroll
        for (int j = 0; j < 4; j++) {
            float4 v = pb[j];
            uint4 u = make_uint4(f2tf(v.x), f2tf(v.y), f2tf(v.z), f2tf(v.w));
            *(uint4*)&Bs[bcin*136 + bseg + j*4] = u;
        }
        if (c + 1 < 8) {
            const float4* bp = (const float4*)(bbase + (c+1) * 32 * SPI);
#pragma unroll
            for (int j = 0; j < 4; j++) pb[j] = bp[j];
        }
        __syncthreads();
#pragma unroll
        for (int ks = 0; ks < 4; ks++) {
            int abase = ((c*4 + ks)*32 + mb*8 + wm*4)*32 + lane;
            uint4 af[4];
#pragma unroll
            for (int mt = 0; mt < 4; mt++) af[mt] = Ab[abase + mt*32];
            unsigned b[4][2];
#pragma unroll
            for (int nt = 0; nt < 4; nt++) {
                int n = wn*32 + nt*8 + g;
                b[nt][0] = Bs[(ks*8 + l4)*136 + n];
                b[nt][1] = Bs[(ks*8 + l4 + 4)*136 + n];
            }
#pragma unroll
            for (int mt = 0; mt < 4; mt++)
#pragma unroll
                for (int nt = 0; nt < 4; nt++)
                    mma8v(acc[mt][nt], af[mt], b[nt][0], b[nt][1]);
        }
        __syncthreads();
    }

#pragma unroll
    for (int mt = 0; mt < 4; mt++)
#pragma unroll
        for (int half = 0; half < 2; half++) {
            int mg = mb*128 + wm*64 + mt*16 + g + half*8;
            float bias = bt[mg];
#pragma unroll
            for (int nt = 0; nt < 4; nt++) {
                int p = pbase + wn*32 + nt*8 + l4*2;
                outb[p*512 + mg]       = acc[mt][nt][half*2]     + bias;
                outb[(p+1)*512 + mg]   = acc[mt][nt][half*2 + 1] + bias;
            }
        }
}

// ---------------- attention (1 warp / token) + BN zeroing fold ----------------
__global__ __launch_bounds__(256) void attn_kernel(int l) {
    if (blockIdx.x == 0) {
        g_bnsum[threadIdx.x] = 0.0f;
        g_bnsq[threadIdx.x] = 0.0f;
    }
    int warp = threadIdx.x >> 5, lane = threadIdx.x & 31;
    int tok = blockIdx.x * 8 + warp;

    float2 q = ((const float2*)&g_q[tok * DHEAD])[lane];
    q.x *= 0.125f; q.y *= 0.125f;

    float sc[5];
#pragma unroll 4
    for (int t = 0; t <= l; t++) {
        float2 kv = ((const float2*)&g_keys[t][tok * DHEAD])[lane];
        float p = q.x * kv.x + q.y * kv.y;
#pragma unroll
        for (int o = 16; o; o >>= 1) p += __shfl_xor_sync(0xffffffffu, p, o);
        sc[t] = p;
    }
    sc[l + 1] = 0.0f;
    int T = l + 2;

    float mx = sc[0];
    for (int t = 1; t < T; t++) mx = fmaxf(mx, sc[t]);
    float e[5], sum = 0.0f;
    for (int t = 0; t < T; t++) { e[t] = expf(sc[t] - mx); sum += e[t]; }
    float inv = 1.0f / sum;
    float a[5];
    for (int t = 0; t < T; t++) a[t] = e[t] * inv;

    if (T == 5) {
        float mn1 = fminf(fminf(a[0], a[1]), fminf(fminf(a[2], a[3]), a[4]));
        float mn2 = 1e30f; bool used = false;
        for (int t = 0; t < 5; t++) {
            if (!used && a[t] == mn1) used = true;
            else mn2 = fminf(mn2, a[t]);
        }
        float delta = mn2 + 1e-7f;
        float s2 = 0.0f;
        for (int t = 0; t < 5; t++) { a[t] = fmaxf(a[t] - delta, 0.0f); s2 += a[t]; }
        float r = 1.0f / (s2 + 1e-7f);
        for (int t = 0; t < 5; t++) a[t] *= r;
    }

    float2 oacc = make_float2(0.0f, 0.0f);
#pragma unroll 4
    for (int t = 0; t <= l; t++) {
        float2 vv = ((const float2*)&g_vals[t][tok * DHEAD])[lane];
        oacc.x += a[t] * vv.x;
        oacc.y += a[t] * vv.y;
    }

    int p = tok >> 3, head = tok & 7;
    int bimg = p >> 10, s = p & 1023;
    float* op = g_o + bimg * (KHH * SPI) + (head * DHEAD + lane * 2) * SPI + s;
    op[0]   = oacc.x;
    op[SPI] = oacc.y;
}

// ---------------- conv1: A frags from g_q; halo prefetch-pipelined -------------
__global__ __launch_bounds__(256) void conv1_gemm(const float* __restrict__ bt) {
    __shared__ unsigned Hs[8*204];
    int tid = threadIdx.x;
    int warp = tid >> 5, lane = tid & 31;
    int g = lane >> 2, l4 = lane & 3;
    int wm = warp & 1, wn = warp >> 1;
    int mbase = blockIdx.y * 128;
    int pbase = blockIdx.x * 128;
    int bimg = pbase >> 10, sbase = pbase & 1023;
    int r0 = sbase >> 5;
    const float* in0 = g_o + bimg * (KHH * SPI);
    const uint4* Ab = (const uint4*)((const unsigned*)g_q + C1_FRAG_OFF);
    int mtb = blockIdx.y * 8;

    int koffA[9], koffB[9];
#pragma unroll
    for (int ks = 0; ks < 9; ks++) {
        int k = ks*8 + l4;
        int cin = k / 9, jj = k - cin*9;
        koffA[ks] = cin*204 + (jj/3)*34 + (jj%3);
        k += 4; cin = k / 9; jj = k - cin*9;
        koffB[ks] = cin*204 + (jj/3)*34 + (jj%3);
    }
    int pixoff[4];
#pragma unroll
    for (int nt = 0; nt < 4; nt++) pixoff[nt] = wn*34 + nt*8 + g;

    // halo offsets (same each chunk)
    int hoff[7];
#pragma unroll
    for (int it = 0; it < 7; it++) {
        int idx = tid + it*256;
        hoff[it] = -1;
        if (idx < 1632) {
            int cin = idx / 204, rem = idx - cin*204;
            int rr = rem / 34, cc = rem - rr*34;
            int yy = r0 - 1 + rr, xx = cc - 1;
            if (yy >= 0 && yy < HH && xx >= 0 && xx < WWW)
                hoff[it] = cin*SPI + yy*WWW + xx;
        }
    }

    float acc[4][4][4];
#pragma unroll
    for (int mt = 0; mt < 4; mt++)
#pragma unroll
        for (int nt = 0; nt < 4; nt++)
#pragma unroll
            for (int r = 0; r < 4; r++) acc[mt][nt][r] = 0.0f;

    float pv[7];
#pragma unroll
    for (int it = 0; it < 7; it++) pv[it] = (hoff[it] >= 0) ? in0[hoff[it]] : 0.0f;

    for (int ch = 0; ch < 64; ch++) {
#pragma unroll
        for (int it = 0; it < 7; it++) {
            int idx = tid + it*256;
            if (idx < 1632) Hs[idx] = f2tf(pv[it]);
        }
        if (ch + 1 < 64) {
            const float* nb = in0 + (ch + 1) * 8 * SPI;
#pragma unroll
            for (int it = 0; it < 7; it++) pv[it] = (hoff[it] >= 0) ? nb[hoff[it]] : 0.0f;
        }
        __syncthreads();
#pragma unroll
        for (int ks = 0; ks < 9; ks++) {
            int abase = ((ch*9 + ks)*16 + mtb + wm*4)*32 + lane;
            uint4 af[4];
#pragma unroll
            for (int mt = 0; mt < 4; mt++) af[mt] = Ab[abase + mt*32];
            unsigned b[4][2];
#pragma unroll
            for (int nt = 0; nt < 4; nt++) {
                b[nt][0] = Hs[koffA[ks] + pixoff[nt]];
                b[nt][1] = Hs[koffB[ks] + pixoff[nt]];
            }
#pragma unroll
            for (int mt = 0; mt < 4; mt++)
#pragma unroll
                for (int nt = 0; nt < 4; nt++)
                    mma8v(acc[mt][nt], af[mt], b[nt][0], b[nt][1]);
        }
        __syncthreads();
    }

    float* hbase = g_h + bimg * (CCH * SPI);
#pragma unroll
    for (int mt = 0; mt < 4; mt++)
#pragma unroll
        for (int half = 0; half < 2; half++) {
            int chn = mbase + wm*64 + mt*16 + g + half*8;
            float bias = bt[chn];
            float s = 0.0f, qq = 0.0f;
#pragma unroll
            for (int nt = 0; nt < 4; nt++) {
                float v0 = acc[mt][nt][half*2]     + bias;
                float v1 = acc[mt][nt][half*2 + 1] + bias;
                int n = wn*32 + nt*8 + l4*2;
                *(float2*)&hbase[chn * SPI + sbase + n] = make_float2(v0, v1);
                s += v0 + v1;
                qq += v0*v0 + v1*v1;
            }
            s  += __shfl_xor_sync(0xffffffffu, s, 1);
            s  += __shfl_xor_sync(0xffffffffu, s, 2);
            qq += __shfl_xor_sync(0xffffffffu, qq, 1);
            qq += __shfl_xor_sync(0xffffffffu, qq, 2);
            if (l4 == 0) {
                atomicAdd(&g_bnsum[chn], s);
                atomicAdd(&g_bnsq[chn], qq);
            }
        }
}

// ---------------- conv2: A frags; BN fin+apply+ReLU; halo prefetch; residual ----
__global__ __launch_bounds__(256) void conv2_gemm(const float* __restrict__ bt,
                                                  const float* __restrict__ bng, const float* __restrict__ bnb,
                                                  const float* __restrict__ gammas, int l) {
    __shared__ unsigned Hs[8*204];
    __shared__ float s_scale[CCH];
    __shared__ float s_shift[CCH];
    int tid = threadIdx.x;
    int warp = tid >> 5, lane = tid & 31;
    int g = lane >> 2, l4 = lane & 3;
    int wm = warp & 1, wn = warp >> 1;
    int mbase = blockIdx.y * 128;
    int pbase = blockIdx.x * 128;
    int bimg = pbase >> 10, sbase = pbase & 1023;
    int r0 = sbase >> 5;
    const float* in0 = g_h + bimg * (CCH * SPI);
    const uint4* Ab = (const uint4*)((const unsigned*)g_q + C2_FRAG_OFF);
    int mtb = blockIdx.y * 8;

    {
        float m = g_bnsum[tid] * (1.0f / (float)NPIX);
        float v = g_bnsq[tid] * (1.0f / (float)NPIX) - m * m;
        float sc = bng[tid] * rsqrtf(v + 1e-5f);
        s_scale[tid] = sc;
        s_shift[tid] = bnb[tid] - m * sc;
    }
    __syncthreads();

    int koffA[9], koffB[9];
#pragma unroll
    for (int ks = 0; ks < 9; ks++) {
        int k = ks*8 + l4;
        int cin = k / 9, jj = k - cin*9;
        koffA[ks] = cin*204 + (jj/3)*34 + (jj%3);
        k += 4; cin = k / 9; jj = k - cin*9;
        koffB[ks] = cin*204 + (jj/3)*34 + (jj%3);
    }
    int pixoff[4];
#pragma unroll
    for (int nt = 0; nt < 4; nt++) pixoff[nt] = wn*34 + nt*8 + g;

    int hoff[7];
#pragma unroll
    for (int it = 0; it < 7; it++) {
        int idx = tid + it*256;
        hoff[it] = -1;
        if (idx < 1632) {
            int cin = idx / 204, rem = idx - cin*204;
            int rr = rem / 34, cc = rem - rr*34;
            int yy = r0 - 1 + rr, xx = cc - 1;
            if (yy >= 0 && yy < HH && xx >= 0 && xx < WWW)
                hoff[it] = cin*SPI + yy*WWW + xx;
        }
    }

    float acc[4][4][4];
#pragma unroll
    for (int mt = 0; mt < 4; mt++)
#pragma unroll
        for (int nt = 0; nt < 4; nt++)
#pragma unroll
            for (int r = 0; r < 4; r++) acc[mt][nt][r] = 0.0f;

    float pv[7];
#pragma unroll
    for (int it = 0; it < 7; it++) pv[it] = (hoff[it] >= 0) ? in0[hoff[it]] : 0.0f;

    for (int ch = 0; ch < 32; ch++) {
#pragma unroll
        for (int it = 0; it < 7; it++) {
            int idx = tid + it*256;
            if (idx < 1632) {
                unsigned val = 0u;
                if (hoff[it] >= 0) {
                    int c = ch*8 + (hoff[it] >> 10);
                    val = f2tf(fmaxf(pv[it] * s_scale[c] + s_shift[c], 0.0f));
                }
                Hs[idx] = val;
            }
        }
        if (ch + 1 < 32) {
            const float* nb = in0 + (ch + 1) * 8 * SPI;
#pragma unroll
            for (int it = 0; it < 7; it++) pv[it] = (hoff[it] >= 0) ? nb[hoff[it]] : 0.0f;
        }
        __syncthreads();
#pragma unroll
        for (int ks = 0; ks < 9; ks++) {
            int abase = ((ch*9 + ks)*16 + mtb + wm*4)*32 + lane;
            uint4 af[4];
#pragma unroll
            for (int mt = 0; mt < 4; mt++) af[mt] = Ab[abase + mt*32];
            unsigned b[4][2];
#pragma unroll
            for (int nt = 0; nt < 4; nt++) {
                b[nt][0] = Hs[koffA[ks] + pixoff[nt]];
                b[nt][1] = Hs[koffB[ks] + pixoff[nt]];
            }
#pragma unroll
            for (int mt = 0; mt < 4; mt++)
#pragma unroll
                for (int nt = 0; nt < 4; nt++)
                    mma8v(acc[mt][nt], af[mt], b[nt][0], b[nt][1]);
        }
        __syncthreads();
    }

    float gam = gammas[l];
    float* xbase = g_x + bimg * (CCH * SPI);
#pragma unroll
    for (int mt = 0; mt < 4; mt++)
#pragma unroll
        for (int half = 0; half < 2; half++) {
            int chn = mbase + wm*64 + mt*16 + g + half*8;
            float bias = bt[chn];
#pragma unroll
            for (int nt = 0; nt < 4; nt++) {
                int n = wn*32 + nt*8 + l4*2;
                float* dst = &xbase[chn * SPI + sbase + n];
                float2 old = *(float2*)dst;
                old.x += gam * (acc[mt][nt][half*2]     + bias);
                old.y += gam * (acc[mt][nt][half*2 + 1] + bias);
                *(float2*)dst = old;
            }
        }
}

// ---------------- launch ----------------
extern "C" void kernel_launch(void* const* d_in, const int* in_sizes, int n_in,
                              void* d_out, int out_size) {
    const float* x   = (const float*)d_in[0];
    const float* kw  = (const float*)d_in[1];
    const float* kb  = (const float*)d_in[2];
    const float* qw  = (const float*)d_in[3];
    const float* qb  = (const float*)d_in[4];
    const float* vw  = (const float*)d_in[5];
    const float* vb  = (const float*)d_in[6];
    const float* ow1 = (const float*)d_in[7];
    const float* ob1 = (const float*)d_in[8];
    const float* bng = (const float*)d_in[9];
    const float* bnb = (const float*)d_in[10];
    const float* ow2 = (const float*)d_in[11];
    const float* ob2 = (const float*)d_in[12];
    const float* gam = (const float*)d_in[13];

    copy_in<<<2048, 256>>>(x);
    for (int l = 0; l < NLAYERS; l++) {
        wconv<<<512, 256>>>(kw + l*KHH*CCH, 0, 0,              256, 32, 32);
        wconv<<<512, 256>>>(qw + l*KHH*CCH, 0, QKV_FRAG_SZ,    256, 32, 32);
        wconv<<<512, 256>>>(vw + l*KHH*CCH, 0, 2*QKV_FRAG_SZ,  256, 32, 32);
        qkv_gemm<<<dim3(64, 12), 256>>>(kb + l*KHH, qb + l*KHH, vb + l*KHH, l);
        attn_kernel<<<8192, 256>>>(l);
        wconv<<<4608, 256>>>(ow1 + l*CCH*KHH*9, 1, C1_FRAG_OFF, 4608, 72, 16);
        wconv<<<2304, 256>>>(ow2 + l*CCH*CCH*9, 1, C2_FRAG_OFF, 2304, 72, 16);
        conv1_gemm<<<dim3(64, 2), 256>>>(ob1 + l*CCH);
        conv2_gemm<<<dim3(64, 2), 256>>>(ob2 + l*CCH, bng + l*CCH, bnb + l*CCH, gam, l);
    }
    copy_out<<<2048, 256>>>((float*)d_out);
}

// round 11
// speedup vs baseline: 3.2995x; 1.0912x over previous
#include <cuda_runtime.h>

#define NLAYERS 4
#define BATCH   8
#define CCH     256
#define HH      32
#define WWW     32
#define NHEADS  8
#define DHEAD   64
#define SPI     1024
#define NPIX    8192
#define NTOK    65536
#define KHH     512

// ---------------- scratch (green overlay set; no new globals) ----------------
__device__ __align__(16) float g_x[BATCH*CCH*SPI];
__device__ __align__(16) float g_keys[NLAYERS][NTOK*DHEAD];
__device__ __align__(16) float g_vals[NLAYERS][NTOK*DHEAD];
__device__ __align__(16) float g_q[NTOK*DHEAD];     // doubles as conv weight-frag scratch
__device__ __align__(16) float g_o[BATCH*KHH*SPI];
__device__ __align__(16) float g_h[BATCH*CCH*SPI];  // doubles as qkv weight-frag scratch
__device__ float g_bnsum[CCH];
__device__ float g_bnsq[CCH];

#define QKV_FRAG_SZ   131072
#define C1_FRAG_OFF   0
#define C2_FRAG_OFF   1179648

// halo geometry for 64-pixel (2-row) tiles: 4 rows x 34 cols per cin, 8 cins
#define HROW 34
#define HCIN 136          // 4*34
#define HTOT 1088         // 8*136

// ---------------- tf32 helpers ----------------
__device__ __forceinline__ unsigned f2tf(float x) {
    unsigned r;
    asm("cvt.rna.tf32.f32 %0, %1;" : "=r"(r) : "f"(x));
    return r;
}
__device__ __forceinline__ void mma8v(float (&d)[4], uint4 a, unsigned b0, unsigned b1) {
    asm volatile(
        "mma.sync.aligned.m16n8k8.row.col.f32.tf32.tf32.f32 "
        "{%0,%1,%2,%3}, {%4,%5,%6,%7}, {%8,%9}, {%0,%1,%2,%3};"
        : "+f"(d[0]), "+f"(d[1]), "+f"(d[2]), "+f"(d[3])
        : "r"(a.x), "r"(a.y), "r"(a.z), "r"(a.w), "r"(b0), "r"(b1));
}

// ---------------- weight conversion (unchanged, green) ----------------
__global__ void wconv(const float* __restrict__ W, int dstSel, int dstOff,
                      int Kdim, int CK, int NMT) {
    unsigned* Wc = (dstSel ? (unsigned*)g_q : (unsigned*)g_h) + dstOff;
    int idx = blockIdx.x * 256 + threadIdx.x;
    int m = idx / Kdim, k = idx - m * Kdim;
    int ch = k / CK, kc = k - ch * CK;
    int ks = kc >> 3, c = kc & 7;
    int KS = CK >> 3;
    int mt = m >> 4, rr = m & 15, gg = rr & 7;
    int lane = gg * 4 + (c & 3);
    int reg = (rr >> 3) + ((c >> 2) << 1);
    Wc[(((ch*KS + ks)*NMT + mt)*32 + lane)*4 + reg] = f2tf(W[idx]);
}

// ---------------- copy in/out ----------------
__global__ void copy_in(const float* __restrict__ x) {
    int i = blockIdx.x * 256 + threadIdx.x;
    ((float4*)g_x)[i] = ((const float4*)x)[i];
}
__global__ void copy_out(float* __restrict__ out) {
    int i = blockIdx.x * 256 + threadIdx.x;
    ((float4*)out)[i] = ((const float4*)g_x)[i];
}

// ---------------- QKV 1x1 conv (unchanged from R10 green) ----------------
__global__ __launch_bounds__(256) void qkv_gemm(
    const float* __restrict__ bk, const float* __restrict__ bq, const float* __restrict__ bv,
    int l)
{
    __shared__ unsigned Bs[32*136];
    int tid = threadIdx.x;
    int warp = tid >> 5, lane = tid & 31;
    int g = lane >> 2, l4 = lane & 3;
    int wm = warp & 1, wn = warp >> 1;
    int by = blockIdx.y, type = by >> 2, mb = by & 3;
    const float* bt = (type == 0) ? bk : ((type == 1) ? bq : bv);
    float* outb = (type == 0) ? g_keys[l] : ((type == 1) ? g_q : g_vals[l]);
    const uint4* Ab = (const uint4*)((const unsigned*)g_h + type * QKV_FRAG_SZ);

    int pbase = blockIdx.x * 128;
    int bimg = pbase >> 10, sbase = pbase & 1023;
    const float* xin = g_x + bimg * (CCH * SPI);

    float acc[4][4][4];
#pragma unroll
    for (int mt = 0; mt < 4; mt++)
#pragma unroll
        for (int nt = 0; nt < 4; nt++)
#pragma unroll
            for (int r = 0; r < 4; r++) acc[mt][nt][r] = 0.0f;

    int bcin = tid >> 3, bseg = (tid & 7) * 16;
    const float* bbase = xin + bcin * SPI + sbase + bseg;

    float4 pb[4];
    {
        const float4* bp = (const float4*)bbase;
#pragma unroll
        for (int j = 0; j < 4; j++) pb[j] = bp[j];
    }

    for (int c = 0; c < 8; c++) {
#pragma unroll
        for (int j = 0; j < 4; j++) {
            float4 v = pb[j];
            uint4 u = make_uint4(f2tf(v.x), f2tf(v.y), f2tf(v.z), f2tf(v.w));
            *(uint4*)&Bs[bcin*136 + bseg + j*4] = u;
        }
        if (c + 1 < 8) {
            const float4* bp = (const float4*)(bbase + (c+1) * 32 * SPI);
#pragma unroll
            for (int j = 0; j < 4; j++) pb[j] = bp[j];
        }
        __syncthreads();
#pragma unroll
        for (int ks = 0; ks < 4; ks++) {
            int abase = ((c*4 + ks)*32 + mb*8 + wm*4)*32 + lane;
            uint4 af[4];
#pragma unroll
            for (int mt = 0; mt < 4; mt++) af[mt] = Ab[abase + mt*32];
            unsigned b[4][2];
#pragma unroll
            for (int nt = 0; nt < 4; nt++) {
                int n = wn*32 + nt*8 + g;
                b[nt][0] = Bs[(ks*8 + l4)*136 + n];
                b[nt][1] = Bs[(ks*8 + l4 + 4)*136 + n];
            }
#pragma unroll
            for (int mt = 0; mt < 4; mt++)
#pragma unroll
                for (int nt = 0; nt < 4; nt++)
                    mma8v(acc[mt][nt], af[mt], b[nt][0], b[nt][1]);
        }
        __syncthreads();
    }

#pragma unroll
    for (int mt = 0; mt < 4; mt++)
#pragma unroll
        for (int half = 0; half < 2; half++) {
            int mg = mb*128 + wm*64 + mt*16 + g + half*8;
            float bias = bt[mg];
#pragma unroll
            for (int nt = 0; nt < 4; nt++) {
                int p = pbase + wn*32 + nt*8 + l4*2;
                outb[p*512 + mg]       = acc[mt][nt][half*2]     + bias;
                outb[(p+1)*512 + mg]   = acc[mt][nt][half*2 + 1] + bias;
            }
        }
}

// ---------------- attention (unchanged) ----------------
__global__ __launch_bounds__(256) void attn_kernel(int l) {
    if (blockIdx.x == 0) {
        g_bnsum[threadIdx.x] = 0.0f;
        g_bnsq[threadIdx.x] = 0.0f;
    }
    int warp = threadIdx.x >> 5, lane = threadIdx.x & 31;
    int tok = blockIdx.x * 8 + warp;

    float2 q = ((const float2*)&g_q[tok * DHEAD])[lane];
    q.x *= 0.125f; q.y *= 0.125f;

    float sc[5];
#pragma unroll 4
    for (int t = 0; t <= l; t++) {
        float2 kv = ((const float2*)&g_keys[t][tok * DHEAD])[lane];
        float p = q.x * kv.x + q.y * kv.y;
#pragma unroll
        for (int o = 16; o; o >>= 1) p += __shfl_xor_sync(0xffffffffu, p, o);
        sc[t] = p;
    }
    sc[l + 1] = 0.0f;
    int T = l + 2;

    float mx = sc[0];
    for (int t = 1; t < T; t++) mx = fmaxf(mx, sc[t]);
    float e[5], sum = 0.0f;
    for (int t = 0; t < T; t++) { e[t] = expf(sc[t] - mx); sum += e[t]; }
    float inv = 1.0f / sum;
    float a[5];
    for (int t = 0; t < T; t++) a[t] = e[t] * inv;

    if (T == 5) {
        float mn1 = fminf(fminf(a[0], a[1]), fminf(fminf(a[2], a[3]), a[4]));
        float mn2 = 1e30f; bool used = false;
        for (int t = 0; t < 5; t++) {
            if (!used && a[t] == mn1) used = true;
            else mn2 = fminf(mn2, a[t]);
        }
        float delta = mn2 + 1e-7f;
        float s2 = 0.0f;
        for (int t = 0; t < 5; t++) { a[t] = fmaxf(a[t] - delta, 0.0f); s2 += a[t]; }
        float r = 1.0f / (s2 + 1e-7f);
        for (int t = 0; t < 5; t++) a[t] *= r;
    }

    float2 oacc = make_float2(0.0f, 0.0f);
#pragma unroll 4
    for (int t = 0; t <= l; t++) {
        float2 vv = ((const float2*)&g_vals[t][tok * DHEAD])[lane];
        oacc.x += a[t] * vv.x;
        oacc.y += a[t] * vv.y;
    }

    int p = tok >> 3, head = tok & 7;
    int bimg = p >> 10, s = p & 1023;
    float* op = g_o + bimg * (KHH * SPI) + (head * DHEAD + lane * 2) * SPI + s;
    op[0]   = oacc.x;
    op[SPI] = oacc.y;
}

// ---------------- conv1: 64-pixel tiles, grid (128,2) -> 2 CTAs/SM -------------
__global__ __launch_bounds__(256) void conv1_gemm(const float* __restrict__ bt) {
    __shared__ unsigned Hs[HTOT];
    int tid = threadIdx.x;
    int warp = tid >> 5, lane = tid & 31;
    int g = lane >> 2, l4 = lane & 3;
    int wm = warp & 1, wn = warp >> 1;
    int mbase = blockIdx.y * 128;
    int pbase = blockIdx.x * 64;
    int bimg = pbase >> 10, sbase = pbase & 1023;
    int r0 = sbase >> 5;                    // first of 2 pixel rows
    const float* in0 = g_o + bimg * (KHH * SPI);
    const uint4* Ab = (const uint4*)((const unsigned*)g_q + C1_FRAG_OFF);
    int mtb = blockIdx.y * 8;
    int pixrow = wn >> 1, pixc0 = (wn & 1) * 16;
    int pixbase = pixrow*HROW + pixc0 + g;  // into halo (before koff's +1row/+1col)

    int koffA[9], koffB[9];
#pragma unroll
    for (int ks = 0; ks < 9; ks++) {
        int k = ks*8 + l4;
        int cin = k / 9, jj = k - cin*9;
        koffA[ks] = cin*HCIN + (jj/3)*HROW + (jj%3);
        k += 4; cin = k / 9; jj = k - cin*9;
        koffB[ks] = cin*HCIN + (jj/3)*HROW + (jj%3);
    }

    // halo offsets: rows r0-1..r0+2, cols -1..32
    int hoff[5];
#pragma unroll
    for (int it = 0; it < 5; it++) {
        int idx = tid + it*256;
        hoff[it] = -1;
        if (idx < HTOT) {
            int cin = idx / HCIN, rem = idx - cin*HCIN;
            int rr = rem / HROW, cc = rem - rr*HROW;
            int yy = r0 - 1 + rr, xx = cc - 1;
            if (yy >= 0 && yy < HH && xx >= 0 && xx < WWW)
                hoff[it] = cin*SPI + yy*WWW + xx;
        }
    }

    float acc[4][2][4];
#pragma unroll
    for (int mt = 0; mt < 4; mt++)
#pragma unroll
        for (int nt = 0; nt < 2; nt++)
#pragma unroll
            for (int r = 0; r < 4; r++) acc[mt][nt][r] = 0.0f;

    float pv[5];
#pragma unroll
    for (int it = 0; it < 5; it++) pv[it] = (hoff[it] >= 0) ? in0[hoff[it]] : 0.0f;

    for (int ch = 0; ch < 64; ch++) {
#pragma unroll
        for (int it = 0; it < 5; it++) {
            int idx = tid + it*256;
            if (idx < HTOT) Hs[idx] = f2tf(pv[it]);
        }
        if (ch + 1 < 64) {
            const float* nb = in0 + (ch + 1) * 8 * SPI;
#pragma unroll
            for (int it = 0; it < 5; it++) pv[it] = (hoff[it] >= 0) ? nb[hoff[it]] : 0.0f;
        }
        __syncthreads();
#pragma unroll
        for (int ks = 0; ks < 9; ks++) {
            int abase = ((ch*9 + ks)*16 + mtb + wm*4)*32 + lane;
            uint4 af[4];
#pragma unroll
            for (int mt = 0; mt < 4; mt++) af[mt] = Ab[abase + mt*32];
            unsigned b[2][2];
#pragma unroll
            for (int nt = 0; nt < 2; nt++) {
                b[nt][0] = Hs[koffA[ks] + pixbase + nt*8];
                b[nt][1] = Hs[koffB[ks] + pixbase + nt*8];
            }
#pragma unroll
            for (int mt = 0; mt < 4; mt++)
#pragma unroll
                for (int nt = 0; nt < 2; nt++)
                    mma8v(acc[mt][nt], af[mt], b[nt][0], b[nt][1]);
        }
        __syncthreads();
    }

    float* hbase = g_h + bimg * (CCH * SPI);
#pragma unroll
    for (int mt = 0; mt < 4; mt++)
#pragma unroll
        for (int half = 0; half < 2; half++) {
            int chn = mbase + wm*64 + mt*16 + g + half*8;
            float bias = bt[chn];
            float s = 0.0f, qq = 0.0f;
#pragma unroll
            for (int nt = 0; nt < 2; nt++) {
                float v0 = acc[mt][nt][half*2]     + bias;
                float v1 = acc[mt][nt][half*2 + 1] + bias;
                int n = pixrow*32 + pixc0 + nt*8 + l4*2;
                *(float2*)&hbase[chn * SPI + sbase + n] = make_float2(v0, v1);
                s += v0 + v1;
                qq += v0*v0 + v1*v1;
            }
            s  += __shfl_xor_sync(0xffffffffu, s, 1);
            s  += __shfl_xor_sync(0xffffffffu, s, 2);
            qq += __shfl_xor_sync(0xffffffffu, qq, 1);
            qq += __shfl_xor_sync(0xffffffffu, qq, 2);
            if (l4 == 0) {
                atomicAdd(&g_bnsum[chn], s);
                atomicAdd(&g_bnsq[chn], qq);
            }
        }
}

// ---------------- conv2: 64-pixel tiles; BN fin+apply+ReLU; residual -----------
__global__ __launch_bounds__(256) void conv2_gemm(const float* __restrict__ bt,
                                                  const float* __restrict__ bng, const float* __restrict__ bnb,
                                                  const float* __restrict__ gammas, int l) {
    __shared__ unsigned Hs[HTOT];
    __shared__ float s_scale[CCH];
    __shared__ float s_shift[CCH];
    int tid = threadIdx.x;
    int warp = tid >> 5, lane = tid & 31;
    int g = lane >> 2, l4 = lane & 3;
    int wm = warp & 1, wn = warp >> 1;
    int mbase = blockIdx.y * 128;
    int pbase = blockIdx.x * 64;
    int bimg = pbase >> 10, sbase = pbase & 1023;
    int r0 = sbase >> 5;
    const float* in0 = g_h + bimg * (CCH * SPI);
    const uint4* Ab = (const uint4*)((const unsigned*)g_q + C2_FRAG_OFF);
    int mtb = blockIdx.y * 8;
    int pixrow = wn >> 1, pixc0 = (wn & 1) * 16;
    int pixbase = pixrow*HROW + pixc0 + g;

    {
        float m = g_bnsum[tid] * (1.0f / (float)NPIX);
        float v = g_bnsq[tid] * (1.0f / (float)NPIX) - m * m;
        float sc = bng[tid] * rsqrtf(v + 1e-5f);
        s_scale[tid] = sc;
        s_shift[tid] = bnb[tid] - m * sc;
    }
    __syncthreads();

    int koffA[9], koffB[9];
#pragma unroll
    for (int ks = 0; ks < 9; ks++) {
        int k = ks*8 + l4;
        int cin = k / 9, jj = k - cin*9;
        koffA[ks] = cin*HCIN + (jj/3)*HROW + (jj%3);
        k += 4; cin = k / 9; jj = k - cin*9;
        koffB[ks] = cin*HCIN + (jj/3)*HROW + (jj%3);
    }

    int hoff[5];
#pragma unroll
    for (int it = 0; it < 5; it++) {
        int idx = tid + it*256;
        hoff[it] = -1;
        if (idx < HTOT) {
            int cin = idx / HCIN, rem = idx - cin*HCIN;
            int rr = rem / HROW, cc = rem - rr*HROW;
            int yy = r0 - 1 + rr, xx = cc - 1;
            if (yy >= 0 && yy < HH && xx >= 0 && xx < WWW)
                hoff[it] = cin*SPI + yy*WWW + xx;
        }
    }

    float acc[4][2][4];
#pragma unroll
    for (int mt = 0; mt < 4; mt++)
#pragma unroll
        for (int nt = 0; nt < 2; nt++)
#pragma unroll
            for (int r = 0; r < 4; r++) acc[mt][nt][r] = 0.0f;

    float pv[5];
#pragma unroll
    for (int it = 0; it < 5; it++) pv[it] = (hoff[it] >= 0) ? in0[hoff[it]] : 0.0f;

    for (int ch = 0; ch < 32; ch++) {
#pragma unroll
        for (int it = 0; it < 5; it++) {
            int idx = tid + it*256;
            if (idx < HTOT) {
                unsigned val = 0u;
                if (hoff[it] >= 0) {
                    int c = ch*8 + (hoff[it] >> 10);
                    val = f2tf(fmaxf(pv[it] * s_scale[c] + s_shift[c], 0.0f));
                }
                Hs[idx] = val;
            }
        }
        if (ch + 1 < 32) {
            const float* nb = in0 + (ch + 1) * 8 * SPI;
#pragma unroll
            for (int it = 0; it < 5; it++) pv[it] = (hoff[it] >= 0) ? nb[hoff[it]] : 0.0f;
        }
        __syncthreads();
#pragma unroll
        for (int ks = 0; ks < 9; ks++) {
            int abase = ((ch*9 + ks)*16 + mtb + wm*4)*32 + lane;
            uint4 af[4];
#pragma unroll
            for (int mt = 0; mt < 4; mt++) af[mt] = Ab[abase + mt*32];
            unsigned b[2][2];
#pragma unroll
            for (int nt = 0; nt < 2; nt++) {
                b[nt][0] = Hs[koffA[ks] + pixbase + nt*8];
                b[nt][1] = Hs[koffB[ks] + pixbase + nt*8];
            }
#pragma unroll
            for (int mt = 0; mt < 4; mt++)
#pragma unroll
                for (int nt = 0; nt < 2; nt++)
                    mma8v(acc[mt][nt], af[mt], b[nt][0], b[nt][1]);
        }
        __syncthreads();
    }

    float gam = gammas[l];
    float* xbase = g_x + bimg * (CCH * SPI);
#pragma unroll
    for (int mt = 0; mt < 4; mt++)
#pragma unroll
        for (int half = 0; half < 2; half++) {
            int chn = mbase + wm*64 + mt*16 + g + half*8;
            float bias = bt[chn];
#pragma unroll
            for (int nt = 0; nt < 2; nt++) {
                int n = pixrow*32 + pixc0 + nt*8 + l4*2;
                float* dst = &xbase[chn * SPI + sbase + n];
                float2 old = *(float2*)dst;
                old.x += gam * (acc[mt][nt][half*2]     + bias);
                old.y += gam * (acc[mt][nt][half*2 + 1] + bias);
                *(float2*)dst = old;
            }
        }
}

// ---------------- launch ----------------
extern "C" void kernel_launch(void* const* d_in, const int* in_sizes, int n_in,
                              void* d_out, int out_size) {
    const float* x   = (const float*)d_in[0];
    const float* kw  = (const float*)d_in[1];
    const float* kb  = (const float*)d_in[2];
    const float* qw  = (const float*)d_in[3];
    const float* qb  = (const float*)d_in[4];
    const float* vw  = (const float*)d_in[5];
    const float* vb  = (const float*)d_in[6];
    const float* ow1 = (const float*)d_in[7];
    const float* ob1 = (const float*)d_in[8];
    const float* bng = (const float*)d_in[9];
    const float* bnb = (const float*)d_in[10];
    const float* ow2 = (const float*)d_in[11];
    const float* ob2 = (const float*)d_in[12];
    const float* gam = (const float*)d_in[13];

    copy_in<<<2048, 256>>>(x);
    for (int l = 0; l < NLAYERS; l++) {
        wconv<<<512, 256>>>(kw + l*KHH*CCH, 0, 0,              256, 32, 32);
        wconv<<<512, 256>>>(qw + l*KHH*CCH, 0, QKV_FRAG_SZ,    256, 32, 32);
        wconv<<<512, 256>>>(vw + l*KHH*CCH, 0, 2*QKV_FRAG_SZ,  256, 32, 32);
        qkv_gemm<<<dim3(64, 12), 256>>>(kb + l*KHH, qb + l*KHH, vb + l*KHH, l);
        attn_kernel<<<8192, 256>>>(l);
        wconv<<<4608, 256>>>(ow1 + l*CCH*KHH*9, 1, C1_FRAG_OFF, 4608, 72, 16);
        wconv<<<2304, 256>>>(ow2 + l*CCH*CCH*9, 1, C2_FRAG_OFF, 2304, 72, 16);
        conv1_gemm<<<dim3(128, 2), 256>>>(ob1 + l*CCH);
        conv2_gemm<<<dim3(128, 2), 256>>>(ob2 + l*CCH, bng + l*CCH, bnb + l*CCH, gam, l);
    }
    copy_out<<<2048, 256>>>((float*)d_out);
}